// round 4
// baseline (speedup 1.0000x reference)
#include <cuda_runtime.h>
#include <cuda_bf16.h>
#include <math.h>

// ---------------------------------------------------------------------------
// Problem constants
// ---------------------------------------------------------------------------
#define BB   2
#define NQ   2048
#define NK   4096
#define DD   512
#define HH   8
#define HID  2048
#define MQ   (BB*NQ)   // 4096
#define MK   (BB*NK)   // 8192

// ---------------------------------------------------------------------------
// Scratch (static device globals; no runtime allocation)
// ---------------------------------------------------------------------------
__device__ __align__(16) float g_q [MQ*DD];
__device__ __align__(16) float g_k [MK*DD];
__device__ __align__(16) float g_v [MK*DD];
__device__ __align__(16) float g_c [MQ*DD];
__device__ __align__(16) float g_xc[MQ*DD];
__device__ __align__(16) float g_xn[MQ*DD];
__device__ __align__(16) float g_y [MQ*DD];
__device__ __align__(16) float g_h1[MQ*HID];

// ---------------------------------------------------------------------------
// GEMM: C[M,N] = A[M,K] @ W[K,N] + bias, optional epilogue
//   epi = 0: none    epi = 1: GELU(exact erf)    epi = 2: + Res[M,N]
// 128x128 tile, BK=8, 256 threads, 8x8 microtile per thread.
// ---------------------------------------------------------------------------
__global__ void __launch_bounds__(256)
gemm128(const float* __restrict__ A, const float* __restrict__ W,
        const float* __restrict__ bias, const float* __restrict__ Res,
        float* __restrict__ C, int M, int N, int K, int epi)
{
    __shared__ __align__(16) float As[8][128];
    __shared__ __align__(16) float Bs[8][128];

    const int tid = threadIdx.x;
    const int m0 = blockIdx.y * 128;
    const int n0 = blockIdx.x * 128;
    const int ty = tid >> 4;          // 0..15 -> rows ty*8..ty*8+7
    const int tx = tid & 15;          // 0..15 -> cols tx*8..tx*8+7

    const int ra = tid >> 1;          // 0..127 : A row within tile
    const int ka = (tid & 1) << 2;    // 0 or 4 : A k-offset
    const int rb = tid >> 5;          // 0..7   : W k-row
    const int cb = (tid & 31) << 2;   // 0..124 : W col offset

    const float* Aptr = A + (size_t)(m0 + ra) * K + ka;
    const float* Bptr = W + (size_t)rb * N + n0 + cb;

    float acc[8][8];
    #pragma unroll
    for (int i = 0; i < 8; ++i)
        #pragma unroll
        for (int j = 0; j < 8; ++j) acc[i][j] = 0.f;

    for (int k0 = 0; k0 < K; k0 += 8) {
        float4 av = *(const float4*)(Aptr + k0);
        float4 bv = *(const float4*)(Bptr + (size_t)k0 * N);
        As[ka + 0][ra] = av.x;
        As[ka + 1][ra] = av.y;
        As[ka + 2][ra] = av.z;
        As[ka + 3][ra] = av.w;
        *(float4*)&Bs[rb][cb] = bv;
        __syncthreads();

        #pragma unroll
        for (int kk = 0; kk < 8; ++kk) {
            float4 a0 = *(const float4*)&As[kk][ty * 8];
            float4 a1 = *(const float4*)&As[kk][ty * 8 + 4];
            float4 b0 = *(const float4*)&Bs[kk][tx * 8];
            float4 b1 = *(const float4*)&Bs[kk][tx * 8 + 4];
            float a[8] = {a0.x, a0.y, a0.z, a0.w, a1.x, a1.y, a1.z, a1.w};
            float b[8] = {b0.x, b0.y, b0.z, b0.w, b1.x, b1.y, b1.z, b1.w};
            #pragma unroll
            for (int i = 0; i < 8; ++i)
                #pragma unroll
                for (int j = 0; j < 8; ++j)
                    acc[i][j] += a[i] * b[j];
        }
        __syncthreads();
    }

    #pragma unroll
    for (int i = 0; i < 8; ++i) {
        const int row = m0 + ty * 8 + i;
        #pragma unroll
        for (int j = 0; j < 8; j += 4) {
            const int col = n0 + tx * 8 + j;
            float4 bsv = *(const float4*)&bias[col];
            float r0 = acc[i][j + 0] + bsv.x;
            float r1 = acc[i][j + 1] + bsv.y;
            float r2 = acc[i][j + 2] + bsv.z;
            float r3 = acc[i][j + 3] + bsv.w;
            if (epi == 1) {
                r0 = 0.5f * r0 * (1.f + erff(r0 * 0.70710678118654752f));
                r1 = 0.5f * r1 * (1.f + erff(r1 * 0.70710678118654752f));
                r2 = 0.5f * r2 * (1.f + erff(r2 * 0.70710678118654752f));
                r3 = 0.5f * r3 * (1.f + erff(r3 * 0.70710678118654752f));
            } else if (epi == 2) {
                float4 rv = *(const float4*)&Res[(size_t)row * N + col];
                r0 += rv.x; r1 += rv.y; r2 += rv.z; r3 += rv.w;
            }
            float4 out = {r0, r1, r2, r3};
            *(float4*)&C[(size_t)row * N + col] = out;
        }
    }
}

// ---------------------------------------------------------------------------
// Flash attention over one (b, h, 64-query tile).
// Q/K/V layout: [(b*Nseq + n), h*64 + dd] with row stride 512.
// 256 threads (16x16), thread owns a 4x4 fragment of the 64x64 tiles.
// smem: Qts[dd][row] (transposed), KVs (K transposed, then V natural), Ps.
// ---------------------------------------------------------------------------
__global__ void __launch_bounds__(256)
attn64(const float* __restrict__ Qg, const float* __restrict__ Kg,
       const float* __restrict__ Vg, float* __restrict__ Og,
       int Nq, int Nk)
{
    __shared__ __align__(16) float Qts[64][64];   // Qts[dd][row]
    __shared__ __align__(16) float KVs[64][64];   // K: [dd][key], V: [key][dd]
    __shared__ __align__(16) float Ps [64][64];   // P[row][key]

    const int tid = threadIdx.x;
    const int ty = tid >> 4, tx = tid & 15;
    const int b = blockIdx.z, h = blockIdx.y;
    const int q0 = blockIdx.x * 64;

    const float* qbase = Qg + (size_t)(b * Nq + q0) * DD + h * 64;
    const float* kbase = Kg + (size_t)b * Nk * DD + h * 64;
    const float* vbase = Vg + (size_t)b * Nk * DD + h * 64;

    // Load Q tile transposed, pre-scaled by d^-0.5 = 0.125
    #pragma unroll
    for (int t = 0; t < 16; ++t) {
        int idx = tid + t * 256;
        int r = idx >> 6, dd = idx & 63;
        Qts[dd][r] = qbase[(size_t)r * DD + dd] * 0.125f;
    }

    float m_i[4], l_i[4], acc[4][4];
    #pragma unroll
    for (int i = 0; i < 4; ++i) {
        m_i[i] = -1e30f; l_i[i] = 0.f;
        #pragma unroll
        for (int j = 0; j < 4; ++j) acc[i][j] = 0.f;
    }

    const int nT = Nk >> 6;
    for (int kb = 0; kb < nT; ++kb) {
        __syncthreads();   // prior P@V done before KVs overwrite

        // Load K tile transposed: KVs[dd][key]
        const float* kt = kbase + (size_t)(kb * 64) * DD;
        #pragma unroll
        for (int t = 0; t < 16; ++t) {
            int idx = tid + t * 256;
            int r = idx >> 6, dd = idx & 63;
            KVs[dd][r] = kt[(size_t)r * DD + dd];
        }
        __syncthreads();

        // S = (Q*scale) @ K^T, 4x4 fragment per thread
        float s[4][4];
        #pragma unroll
        for (int i = 0; i < 4; ++i)
            #pragma unroll
            for (int j = 0; j < 4; ++j) s[i][j] = 0.f;

        #pragma unroll 8
        for (int dd = 0; dd < 64; ++dd) {
            float4 qv = *(const float4*)&Qts[dd][ty * 4];
            float4 kv = *(const float4*)&KVs[dd][tx * 4];
            float qa[4] = {qv.x, qv.y, qv.z, qv.w};
            float ka[4] = {kv.x, kv.y, kv.z, kv.w};
            #pragma unroll
            for (int i = 0; i < 4; ++i)
                #pragma unroll
                for (int j = 0; j < 4; ++j)
                    s[i][j] += qa[i] * ka[j];
        }

        // Online softmax (rows shared by the 16 tx lanes of each 16-lane group)
        #pragma unroll
        for (int i = 0; i < 4; ++i) {
            float rmax = fmaxf(fmaxf(s[i][0], s[i][1]), fmaxf(s[i][2], s[i][3]));
            rmax = fmaxf(rmax, __shfl_xor_sync(0xffffffffu, rmax, 1));
            rmax = fmaxf(rmax, __shfl_xor_sync(0xffffffffu, rmax, 2));
            rmax = fmaxf(rmax, __shfl_xor_sync(0xffffffffu, rmax, 4));
            rmax = fmaxf(rmax, __shfl_xor_sync(0xffffffffu, rmax, 8));
            float mnew = fmaxf(m_i[i], rmax);
            float corr = __expf(m_i[i] - mnew);
            float rs = 0.f;
            #pragma unroll
            for (int j = 0; j < 4; ++j) {
                float p = __expf(s[i][j] - mnew);
                Ps[ty * 4 + i][tx * 4 + j] = p;
                rs += p;
            }
            rs += __shfl_xor_sync(0xffffffffu, rs, 1);
            rs += __shfl_xor_sync(0xffffffffu, rs, 2);
            rs += __shfl_xor_sync(0xffffffffu, rs, 4);
            rs += __shfl_xor_sync(0xffffffffu, rs, 8);
            l_i[i] = l_i[i] * corr + rs;
            m_i[i] = mnew;
            #pragma unroll
            for (int j = 0; j < 4; ++j) acc[i][j] *= corr;
        }
        __syncthreads();   // Ps written; S-GEMM reads of KVs (K) done

        // Load V tile natural: KVs[key][dd]
        const float* vt = vbase + (size_t)(kb * 64) * DD;
        #pragma unroll
        for (int t = 0; t < 16; ++t) {
            int idx = tid + t * 256;
            int r = idx >> 6, dd = idx & 63;
            KVs[r][dd] = vt[(size_t)r * DD + dd];
        }
        __syncthreads();

        // acc += P @ V
        #pragma unroll 8
        for (int k = 0; k < 64; ++k) {
            float4 vv = *(const float4*)&KVs[k][tx * 4];
            float va[4] = {vv.x, vv.y, vv.z, vv.w};
            #pragma unroll
            for (int i = 0; i < 4; ++i) {
                float p = Ps[ty * 4 + i][k];
                #pragma unroll
                for (int j = 0; j < 4; ++j)
                    acc[i][j] += p * va[j];
            }
        }
    }

    // Normalize and write out
    #pragma unroll
    for (int i = 0; i < 4; ++i) {
        float inv = 1.0f / l_i[i];
        float4 o;
        o.x = acc[i][0] * inv;
        o.y = acc[i][1] * inv;
        o.z = acc[i][2] * inv;
        o.w = acc[i][3] * inv;
        *(float4*)&Og[(size_t)(b * Nq + q0 + ty * 4 + i) * DD + h * 64 + tx * 4] = o;
    }
}

// ---------------------------------------------------------------------------
// LayerNorm over last dim (512), biased variance, eps=1e-5.
// One row per block, 128 threads, one float4 per thread.
// ---------------------------------------------------------------------------
__global__ void __launch_bounds__(128)
layernorm_k(const float* __restrict__ X, const float* __restrict__ gam,
            const float* __restrict__ bet, float* __restrict__ Y)
{
    __shared__ float red[8];
    const int row = blockIdx.x, tid = threadIdx.x;
    float4 v = *(const float4*)&X[(size_t)row * DD + tid * 4];
    float s  = v.x + v.y + v.z + v.w;
    float ss = v.x * v.x + v.y * v.y + v.z * v.z + v.w * v.w;
    #pragma unroll
    for (int o = 16; o; o >>= 1) {
        s  += __shfl_xor_sync(0xffffffffu, s, o);
        ss += __shfl_xor_sync(0xffffffffu, ss, o);
    }
    if ((tid & 31) == 0) { red[tid >> 5] = s; red[4 + (tid >> 5)] = ss; }
    __syncthreads();
    s  = red[0] + red[1] + red[2] + red[3];
    ss = red[4] + red[5] + red[6] + red[7];
    float mean = s * (1.f / 512.f);
    float var  = ss * (1.f / 512.f) - mean * mean;
    float rstd = rsqrtf(var + 1e-5f);
    float4 g4 = *(const float4*)&gam[tid * 4];
    float4 b4 = *(const float4*)&bet[tid * 4];
    float4 o;
    o.x = (v.x - mean) * rstd * g4.x + b4.x;
    o.y = (v.y - mean) * rstd * g4.y + b4.y;
    o.z = (v.z - mean) * rstd * g4.z + b4.z;
    o.w = (v.w - mean) * rstd * g4.w + b4.w;
    *(float4*)&Y[(size_t)row * DD + tid * 4] = o;
}

// ---------------------------------------------------------------------------
// Host orchestration (graph-capturable: kernel launches only)
// ---------------------------------------------------------------------------
extern "C" void kernel_launch(void* const* d_in, const int* in_sizes, int n_in,
                              void* d_out, int out_size)
{
    const float* x      = (const float*)d_in[0];
    const float* cross  = (const float*)d_in[1];
    const float* ca_wq  = (const float*)d_in[2];
    const float* ca_bq  = (const float*)d_in[3];
    const float* ca_wk  = (const float*)d_in[4];
    const float* ca_bk  = (const float*)d_in[5];
    const float* ca_wv  = (const float*)d_in[6];
    const float* ca_bv  = (const float*)d_in[7];
    const float* ca_wo  = (const float*)d_in[8];
    const float* ca_bo  = (const float*)d_in[9];
    const float* sa_wq  = (const float*)d_in[10];
    const float* sa_bq  = (const float*)d_in[11];
    const float* sa_wk  = (const float*)d_in[12];
    const float* sa_bk  = (const float*)d_in[13];
    const float* sa_wv  = (const float*)d_in[14];
    const float* sa_bv  = (const float*)d_in[15];
    const float* sa_wo  = (const float*)d_in[16];
    const float* sa_bo  = (const float*)d_in[17];
    const float* ln1_g  = (const float*)d_in[18];
    const float* ln1_b  = (const float*)d_in[19];
    const float* ln2_g  = (const float*)d_in[20];
    const float* ln2_b  = (const float*)d_in[21];
    const float* mlp_w1 = (const float*)d_in[22];
    const float* mlp_b1 = (const float*)d_in[23];
    const float* mlp_w2 = (const float*)d_in[24];
    const float* mlp_b2 = (const float*)d_in[25];
    float* out = (float*)d_out;

    float *q, *k, *v, *c, *xc, *xn, *y, *h1;
    cudaGetSymbolAddress((void**)&q,  g_q);
    cudaGetSymbolAddress((void**)&k,  g_k);
    cudaGetSymbolAddress((void**)&v,  g_v);
    cudaGetSymbolAddress((void**)&c,  g_c);
    cudaGetSymbolAddress((void**)&xc, g_xc);
    cudaGetSymbolAddress((void**)&xn, g_xn);
    cudaGetSymbolAddress((void**)&y,  g_y);
    cudaGetSymbolAddress((void**)&h1, g_h1);

    const dim3 blk(256);
    const dim3 gq(DD / 128, MQ / 128);    // 4 x 32
    const dim3 gk(DD / 128, MK / 128);    // 4 x 64
    const dim3 gh(HID / 128, MQ / 128);   // 16 x 32
    const dim3 ga(NQ / 64, HH, BB);       // 32 x 8 x 2

    // ---- cross-attention ----
    gemm128<<<gq, blk>>>(x,     ca_wq, ca_bq, nullptr, q, MQ, DD, DD, 0);
    gemm128<<<gk, blk>>>(cross, ca_wk, ca_bk, nullptr, k, MK, DD, DD, 0);
    gemm128<<<gk, blk>>>(cross, ca_wv, ca_bv, nullptr, v, MK, DD, DD, 0);
    attn64<<<ga, blk>>>(q, k, v, c, NQ, NK);
    gemm128<<<gq, blk>>>(c, ca_wo, ca_bo, nullptr, xc, MQ, DD, DD, 0);

    // ---- LN1 + self-attention ----
    layernorm_k<<<MQ, 128>>>(xc, ln1_g, ln1_b, xn);
    gemm128<<<gq, blk>>>(xn, sa_wq, sa_bq, nullptr, q, MQ, DD, DD, 0);
    gemm128<<<gq, blk>>>(xn, sa_wk, sa_bk, nullptr, k, MQ, DD, DD, 0);
    gemm128<<<gq, blk>>>(xn, sa_wv, sa_bv, nullptr, v, MQ, DD, DD, 0);
    attn64<<<ga, blk>>>(q, k, v, c, NQ, NQ);
    gemm128<<<gq, blk>>>(c, sa_wo, sa_bo, xc, y, MQ, DD, DD, 2);   // y = xc + xs

    // ---- LN2 + MLP + residual ----
    layernorm_k<<<MQ, 128>>>(y, ln2_g, ln2_b, xn);
    gemm128<<<gh, blk>>>(xn, mlp_w1, mlp_b1, nullptr, h1, MQ, HID, DD, 1);  // GELU
    gemm128<<<gq, blk>>>(h1, mlp_w2, mlp_b2, y, out, MQ, DD, HID, 2);       // + y
}

// round 7
// speedup vs baseline: 3.7288x; 3.7288x over previous
#include <cuda_runtime.h>
#include <cuda_bf16.h>
#include <math.h>
#include <stdint.h>

// ---------------------------------------------------------------------------
// Problem constants
// ---------------------------------------------------------------------------
#define BB   2
#define NQ   2048
#define NK   4096
#define DD   512
#define HH   8
#define HID  2048
#define MQ   (BB*NQ)   // 4096
#define MK   (BB*NK)   // 8192

// ---------------------------------------------------------------------------
// Scratch (static device globals; no runtime allocation)
// ---------------------------------------------------------------------------
__device__ __align__(16) float g_q [MQ*DD];
__device__ __align__(16) float g_k [MK*DD];
__device__ __align__(16) float g_v [MK*DD];
__device__ __align__(16) float g_c [MQ*DD];
__device__ __align__(16) float g_xc[MQ*DD];
__device__ __align__(16) float g_xn[MQ*DD];
__device__ __align__(16) float g_y [MQ*DD];
__device__ __align__(16) float g_h1[MQ*HID];

// ---------------------------------------------------------------------------
// mma.sync helpers (portable tensor-core path; works on plain sm_103 target)
// ---------------------------------------------------------------------------
__device__ __forceinline__ uint32_t tf32r(float x) {
    uint32_t u;
    asm("cvt.rna.tf32.f32 %0, %1;" : "=r"(u) : "f"(x));
    return u;
}

__device__ __forceinline__ void mma_tf32(float c[4],
                                         uint32_t a0, uint32_t a1,
                                         uint32_t a2, uint32_t a3,
                                         uint32_t b0, uint32_t b1)
{
    asm volatile(
        "mma.sync.aligned.m16n8k8.row.col.f32.tf32.tf32.f32 "
        "{%0,%1,%2,%3}, {%4,%5,%6,%7}, {%8,%9}, {%0,%1,%2,%3};"
        : "+f"(c[0]), "+f"(c[1]), "+f"(c[2]), "+f"(c[3])
        : "r"(a0), "r"(a1), "r"(a2), "r"(a3), "r"(b0), "r"(b1));
}

__device__ __forceinline__ uint32_t fbits(float x) { return __float_as_uint(x); }

// ---------------------------------------------------------------------------
// tf32 tensor-core GEMM: C[M,N] = A[M,K] @ W[K,N] + bias, epilogue
//   epi = 0: none   epi = 1: GELU(erf)   epi = 2: + Res
// CTA tile 128x128, BK=32. 256 threads = 8 warps as 4(m) x 2(n),
// warp tile 32x64 = 2 m-tiles x 8 n-tiles of m16n8k8.
// A smem stride 36 (bank-free: 4g+t), W smem stride 136 (bank-free: 8t+g).
// ---------------------------------------------------------------------------
__global__ void __launch_bounds__(256)
gemm_mma(const float* __restrict__ A, const float* __restrict__ W,
         const float* __restrict__ bias, const float* __restrict__ Res,
         float* __restrict__ C, int M, int N, int K, int epi)
{
    __shared__ float As[128 * 36];
    __shared__ float Ws[32 * 136];

    const int tid = threadIdx.x;
    const int wid = tid >> 5, lane = tid & 31;
    const int g = lane >> 2, t = lane & 3;
    const int wm = wid >> 1, wn = wid & 1;
    const int m0 = blockIdx.y * 128, n0 = blockIdx.x * 128;

    float acc[2][8][4];
    #pragma unroll
    for (int mt = 0; mt < 2; ++mt)
        #pragma unroll
        for (int nt = 0; nt < 8; ++nt)
            #pragma unroll
            for (int j = 0; j < 4; ++j) acc[mt][nt][j] = 0.f;

    for (int kc = 0; kc < K; kc += 32) {
        // A: 128 rows x 32 floats (8 float4/row), K-major coalesced
        #pragma unroll
        for (int it = 0; it < 4; ++it) {
            int idx = tid + it * 256;
            int r = idx >> 3, c4 = idx & 7;
            float4 v = *(const float4*)(A + (size_t)(m0 + r) * K + kc + c4 * 4);
            float* p = &As[r * 36 + c4 * 4];
            p[0] = __uint_as_float(tf32r(v.x));
            p[1] = __uint_as_float(tf32r(v.y));
            p[2] = __uint_as_float(tf32r(v.z));
            p[3] = __uint_as_float(tf32r(v.w));
        }
        // W: 32 rows x 128 floats (32 float4/row), N contiguous coalesced
        #pragma unroll
        for (int it = 0; it < 4; ++it) {
            int idx = tid + it * 256;
            int r = idx >> 5, c4 = idx & 31;
            float4 v = *(const float4*)(W + (size_t)(kc + r) * N + n0 + c4 * 4);
            float* p = &Ws[r * 136 + c4 * 4];
            p[0] = __uint_as_float(tf32r(v.x));
            p[1] = __uint_as_float(tf32r(v.y));
            p[2] = __uint_as_float(tf32r(v.z));
            p[3] = __uint_as_float(tf32r(v.w));
        }
        __syncthreads();

        #pragma unroll
        for (int kk = 0; kk < 4; ++kk) {
            const int k0 = kk * 8;
            uint32_t a[2][4];
            #pragma unroll
            for (int mt = 0; mt < 2; ++mt) {
                const int rb = wm * 32 + mt * 16;
                a[mt][0] = fbits(As[(rb + g    ) * 36 + k0 + t    ]);
                a[mt][1] = fbits(As[(rb + g + 8) * 36 + k0 + t    ]);
                a[mt][2] = fbits(As[(rb + g    ) * 36 + k0 + t + 4]);
                a[mt][3] = fbits(As[(rb + g + 8) * 36 + k0 + t + 4]);
            }
            #pragma unroll
            for (int nt = 0; nt < 8; ++nt) {
                uint32_t b0 = fbits(Ws[(k0 + t    ) * 136 + wn * 64 + nt * 8 + g]);
                uint32_t b1 = fbits(Ws[(k0 + t + 4) * 136 + wn * 64 + nt * 8 + g]);
                mma_tf32(acc[0][nt], a[0][0], a[0][1], a[0][2], a[0][3], b0, b1);
                mma_tf32(acc[1][nt], a[1][0], a[1][1], a[1][2], a[1][3], b0, b1);
            }
        }
        __syncthreads();
    }

    // Epilogue. c0,c1 -> (row, col..col+1); c2,c3 -> (row+8, same cols)
    #pragma unroll
    for (int mt = 0; mt < 2; ++mt) {
        #pragma unroll
        for (int nt = 0; nt < 8; ++nt) {
            const int row = m0 + wm * 32 + mt * 16 + g;
            const int col = n0 + wn * 64 + nt * 8 + 2 * t;
            const float bs0 = __ldg(&bias[col]);
            const float bs1 = __ldg(&bias[col + 1]);
            float r0 = acc[mt][nt][0] + bs0;
            float r1 = acc[mt][nt][1] + bs1;
            float r2 = acc[mt][nt][2] + bs0;
            float r3 = acc[mt][nt][3] + bs1;
            if (epi == 1) {
                r0 = 0.5f * r0 * (1.f + erff(r0 * 0.70710678118654752f));
                r1 = 0.5f * r1 * (1.f + erff(r1 * 0.70710678118654752f));
                r2 = 0.5f * r2 * (1.f + erff(r2 * 0.70710678118654752f));
                r3 = 0.5f * r3 * (1.f + erff(r3 * 0.70710678118654752f));
            } else if (epi == 2) {
                float2 u = *(const float2*)&Res[(size_t)row * N + col];
                float2 w = *(const float2*)&Res[(size_t)(row + 8) * N + col];
                r0 += u.x; r1 += u.y; r2 += w.x; r3 += w.y;
            }
            float2 o0 = {r0, r1}, o1 = {r2, r3};
            *(float2*)&C[(size_t)row * N + col] = o0;
            *(float2*)&C[(size_t)(row + 8) * N + col] = o1;
        }
    }
}

// ---------------------------------------------------------------------------
// Flash attention, tf32 mma. One (b, h, 64-query tile) per CTA, 128 threads,
// 4 warps x 16 query rows. S and P@V on m16n8k8.
// Smem: Qs stride 68 | KV (K as stride-68 view, V as stride-72 view) | Ps 68.
// All fragment reads bank-conflict-free by stride construction.
// ---------------------------------------------------------------------------
#define ATT_SMEM ((64*68 + 64*72 + 64*68) * 4)

__global__ void __launch_bounds__(128)
attn_mma(const float* __restrict__ Qg, const float* __restrict__ Kg,
         const float* __restrict__ Vg, float* __restrict__ Og,
         int Nq, int Nk)
{
    extern __shared__ float sm[];
    float* Qs = sm;                        // [64][68]
    float* KV = sm + 64 * 68;              // K:[64][68]  V:[64][72]
    float* Ps = sm + 64 * 68 + 64 * 72;    // [64][68]

    const int tid = threadIdx.x;
    const int wid = tid >> 5, lane = tid & 31;
    const int g = lane >> 2, t = lane & 3;
    const int b = blockIdx.z, h = blockIdx.y;
    const int q0 = blockIdx.x * 64;

    const float* qbase = Qg + (size_t)(b * Nq + q0) * DD + h * 64;
    const float* kbase = Kg + (size_t)b * Nk * DD + h * 64;
    const float* vbase = Vg + (size_t)b * Nk * DD + h * 64;

    // Q tile, pre-scaled by d^-0.5 = 0.125 (exact), tf32-rounded
    #pragma unroll
    for (int it = 0; it < 8; ++it) {
        int idx = tid + it * 128;
        int r = idx >> 4, c4 = idx & 15;
        float4 v = *(const float4*)(qbase + (size_t)r * DD + c4 * 4);
        float* p = &Qs[r * 68 + c4 * 4];
        p[0] = __uint_as_float(tf32r(v.x * 0.125f));
        p[1] = __uint_as_float(tf32r(v.y * 0.125f));
        p[2] = __uint_as_float(tf32r(v.z * 0.125f));
        p[3] = __uint_as_float(tf32r(v.w * 0.125f));
    }

    float mr0 = -1e30f, mr1 = -1e30f, l0 = 0.f, l1 = 0.f;
    float o[8][4];
    #pragma unroll
    for (int nt = 0; nt < 8; ++nt)
        #pragma unroll
        for (int j = 0; j < 4; ++j) o[nt][j] = 0.f;

    const int rowA = wid * 16 + g;      // this thread's upper A row
    const int nT = Nk >> 6;

    for (int kb = 0; kb < nT; ++kb) {
        __syncthreads();   // prior P@V reads of KV/Ps done (1st iter: Qs ready below)

        // K tile (natural [key][d]), stride 68
        const float* kt = kbase + (size_t)(kb * 64) * DD;
        #pragma unroll
        for (int it = 0; it < 8; ++it) {
            int idx = tid + it * 128;
            int r = idx >> 4, c4 = idx & 15;
            float4 v = *(const float4*)(kt + (size_t)r * DD + c4 * 4);
            float* p = &KV[r * 68 + c4 * 4];
            p[0] = __uint_as_float(tf32r(v.x));
            p[1] = __uint_as_float(tf32r(v.y));
            p[2] = __uint_as_float(tf32r(v.z));
            p[3] = __uint_as_float(tf32r(v.w));
        }
        __syncthreads();

        // S = Q @ K^T  (64x64, warp does 16 rows x 64 keys)
        float s[8][4];
        #pragma unroll
        for (int nt = 0; nt < 8; ++nt)
            #pragma unroll
            for (int j = 0; j < 4; ++j) s[nt][j] = 0.f;

        #pragma unroll
        for (int kk = 0; kk < 8; ++kk) {
            const int k0 = kk * 8;
            uint32_t a0 = fbits(Qs[(rowA    ) * 68 + k0 + t    ]);
            uint32_t a1 = fbits(Qs[(rowA + 8) * 68 + k0 + t    ]);
            uint32_t a2 = fbits(Qs[(rowA    ) * 68 + k0 + t + 4]);
            uint32_t a3 = fbits(Qs[(rowA + 8) * 68 + k0 + t + 4]);
            #pragma unroll
            for (int nt = 0; nt < 8; ++nt) {
                uint32_t b0 = fbits(KV[(nt * 8 + g) * 68 + k0 + t    ]);
                uint32_t b1 = fbits(KV[(nt * 8 + g) * 68 + k0 + t + 4]);
                mma_tf32(s[nt], a0, a1, a2, a3, b0, b1);
            }
        }

        // Online softmax. Thread owns rows (rowA, rowA+8); row elements are
        // spread over the 4 lanes t of this group -> shfl_xor 1,2 reduces.
        float rmax0 = -1e30f, rmax1 = -1e30f;
        #pragma unroll
        for (int nt = 0; nt < 8; ++nt) {
            rmax0 = fmaxf(rmax0, fmaxf(s[nt][0], s[nt][1]));
            rmax1 = fmaxf(rmax1, fmaxf(s[nt][2], s[nt][3]));
        }
        rmax0 = fmaxf(rmax0, __shfl_xor_sync(0xffffffffu, rmax0, 1));
        rmax0 = fmaxf(rmax0, __shfl_xor_sync(0xffffffffu, rmax0, 2));
        rmax1 = fmaxf(rmax1, __shfl_xor_sync(0xffffffffu, rmax1, 1));
        rmax1 = fmaxf(rmax1, __shfl_xor_sync(0xffffffffu, rmax1, 2));

        const float mn0 = fmaxf(mr0, rmax0);
        const float mn1 = fmaxf(mr1, rmax1);
        const float corr0 = __expf(mr0 - mn0);
        const float corr1 = __expf(mr1 - mn1);

        float rs0 = 0.f, rs1 = 0.f;
        #pragma unroll
        for (int nt = 0; nt < 8; ++nt) {
            float p0 = __expf(s[nt][0] - mn0);
            float p1 = __expf(s[nt][1] - mn0);
            float p2 = __expf(s[nt][2] - mn1);
            float p3 = __expf(s[nt][3] - mn1);
            rs0 += p0 + p1;
            rs1 += p2 + p3;
            const int col = nt * 8 + 2 * t;
            float2 w0 = {__uint_as_float(tf32r(p0)), __uint_as_float(tf32r(p1))};
            float2 w1 = {__uint_as_float(tf32r(p2)), __uint_as_float(tf32r(p3))};
            *(float2*)&Ps[(rowA    ) * 68 + col] = w0;
            *(float2*)&Ps[(rowA + 8) * 68 + col] = w1;
        }
        rs0 += __shfl_xor_sync(0xffffffffu, rs0, 1);
        rs0 += __shfl_xor_sync(0xffffffffu, rs0, 2);
        rs1 += __shfl_xor_sync(0xffffffffu, rs1, 1);
        rs1 += __shfl_xor_sync(0xffffffffu, rs1, 2);

        l0 = l0 * corr0 + rs0;
        l1 = l1 * corr1 + rs1;
        mr0 = mn0; mr1 = mn1;
        #pragma unroll
        for (int nt = 0; nt < 8; ++nt) {
            o[nt][0] *= corr0; o[nt][1] *= corr0;
            o[nt][2] *= corr1; o[nt][3] *= corr1;
        }
        __syncthreads();   // all warps done reading K before V overwrite

        // V tile (natural [key][d]), stride 72
        const float* vt = vbase + (size_t)(kb * 64) * DD;
        #pragma unroll
        for (int it = 0; it < 8; ++it) {
            int idx = tid + it * 128;
            int r = idx >> 4, c4 = idx & 15;
            float4 v = *(const float4*)(vt + (size_t)r * DD + c4 * 4);
            float* p = &KV[r * 72 + c4 * 4];
            p[0] = __uint_as_float(tf32r(v.x));
            p[1] = __uint_as_float(tf32r(v.y));
            p[2] = __uint_as_float(tf32r(v.z));
            p[3] = __uint_as_float(tf32r(v.w));
        }
        __syncthreads();

        // O += P @ V  (K dim = keys)
        #pragma unroll
        for (int kk = 0; kk < 8; ++kk) {
            const int k0 = kk * 8;
            uint32_t a0 = fbits(Ps[(rowA    ) * 68 + k0 + t    ]);
            uint32_t a1 = fbits(Ps[(rowA + 8) * 68 + k0 + t    ]);
            uint32_t a2 = fbits(Ps[(rowA    ) * 68 + k0 + t + 4]);
            uint32_t a3 = fbits(Ps[(rowA + 8) * 68 + k0 + t + 4]);
            #pragma unroll
            for (int nt = 0; nt < 8; ++nt) {
                uint32_t b0 = fbits(KV[(k0 + t    ) * 72 + nt * 8 + g]);
                uint32_t b1 = fbits(KV[(k0 + t + 4) * 72 + nt * 8 + g]);
                mma_tf32(o[nt], a0, a1, a2, a3, b0, b1);
            }
        }
    }

    // Normalize + write
    const float inv0 = 1.0f / l0;
    const float inv1 = 1.0f / l1;
    const int r0g = b * Nq + q0 + rowA;
    #pragma unroll
    for (int nt = 0; nt < 8; ++nt) {
        const int col = h * 64 + nt * 8 + 2 * t;
        float2 w0 = {o[nt][0] * inv0, o[nt][1] * inv0};
        float2 w1 = {o[nt][2] * inv1, o[nt][3] * inv1};
        *(float2*)&Og[(size_t)r0g * DD + col] = w0;
        *(float2*)&Og[(size_t)(r0g + 8) * DD + col] = w1;
    }
}

// ---------------------------------------------------------------------------
// LayerNorm over last dim (512), biased variance, eps=1e-5.
// ---------------------------------------------------------------------------
__global__ void __launch_bounds__(128)
layernorm_k(const float* __restrict__ X, const float* __restrict__ gam,
            const float* __restrict__ bet, float* __restrict__ Y)
{
    __shared__ float red[8];
    const int row = blockIdx.x, tid = threadIdx.x;
    float4 v = *(const float4*)&X[(size_t)row * DD + tid * 4];
    float s  = v.x + v.y + v.z + v.w;
    float ss = v.x * v.x + v.y * v.y + v.z * v.z + v.w * v.w;
    #pragma unroll
    for (int o = 16; o; o >>= 1) {
        s  += __shfl_xor_sync(0xffffffffu, s, o);
        ss += __shfl_xor_sync(0xffffffffu, ss, o);
    }
    if ((tid & 31) == 0) { red[tid >> 5] = s; red[4 + (tid >> 5)] = ss; }
    __syncthreads();
    s  = red[0] + red[1] + red[2] + red[3];
    ss = red[4] + red[5] + red[6] + red[7];
    float mean = s * (1.f / 512.f);
    float var  = ss * (1.f / 512.f) - mean * mean;
    float rstd = rsqrtf(var + 1e-5f);
    float4 g4 = *(const float4*)&gam[tid * 4];
    float4 b4 = *(const float4*)&bet[tid * 4];
    float4 o;
    o.x = (v.x - mean) * rstd * g4.x + b4.x;
    o.y = (v.y - mean) * rstd * g4.y + b4.y;
    o.z = (v.z - mean) * rstd * g4.z + b4.z;
    o.w = (v.w - mean) * rstd * g4.w + b4.w;
    *(float4*)&Y[(size_t)row * DD + tid * 4] = o;
}

// ---------------------------------------------------------------------------
// Host orchestration (graph-capturable: kernel launches only)
// ---------------------------------------------------------------------------
extern "C" void kernel_launch(void* const* d_in, const int* in_sizes, int n_in,
                              void* d_out, int out_size)
{
    const float* x      = (const float*)d_in[0];
    const float* cross  = (const float*)d_in[1];
    const float* ca_wq  = (const float*)d_in[2];
    const float* ca_bq  = (const float*)d_in[3];
    const float* ca_wk  = (const float*)d_in[4];
    const float* ca_bk  = (const float*)d_in[5];
    const float* ca_wv  = (const float*)d_in[6];
    const float* ca_bv  = (const float*)d_in[7];
    const float* ca_wo  = (const float*)d_in[8];
    const float* ca_bo  = (const float*)d_in[9];
    const float* sa_wq  = (const float*)d_in[10];
    const float* sa_bq  = (const float*)d_in[11];
    const float* sa_wk  = (const float*)d_in[12];
    const float* sa_bk  = (const float*)d_in[13];
    const float* sa_wv  = (const float*)d_in[14];
    const float* sa_bv  = (const float*)d_in[15];
    const float* sa_wo  = (const float*)d_in[16];
    const float* sa_bo  = (const float*)d_in[17];
    const float* ln1_g  = (const float*)d_in[18];
    const float* ln1_b  = (const float*)d_in[19];
    const float* ln2_g  = (const float*)d_in[20];
    const float* ln2_b  = (const float*)d_in[21];
    const float* mlp_w1 = (const float*)d_in[22];
    const float* mlp_b1 = (const float*)d_in[23];
    const float* mlp_w2 = (const float*)d_in[24];
    const float* mlp_b2 = (const float*)d_in[25];
    float* out = (float*)d_out;

    float *q, *k, *v, *c, *xc, *xn, *y, *h1;
    cudaGetSymbolAddress((void**)&q,  g_q);
    cudaGetSymbolAddress((void**)&k,  g_k);
    cudaGetSymbolAddress((void**)&v,  g_v);
    cudaGetSymbolAddress((void**)&c,  g_c);
    cudaGetSymbolAddress((void**)&xc, g_xc);
    cudaGetSymbolAddress((void**)&xn, g_xn);
    cudaGetSymbolAddress((void**)&y,  g_y);
    cudaGetSymbolAddress((void**)&h1, g_h1);

    cudaFuncSetAttribute(attn_mma, cudaFuncAttributeMaxDynamicSharedMemorySize,
                         ATT_SMEM);

    const dim3 blk(256);
    const dim3 gq(DD / 128, MQ / 128);    // 4 x 32
    const dim3 gk(DD / 128, MK / 128);    // 4 x 64
    const dim3 gh(HID / 128, MQ / 128);   // 16 x 32
    const dim3 ga(NQ / 64, HH, BB);       // 32 x 8 x 2

    // ---- cross-attention ----
    gemm_mma<<<gq, blk>>>(x,     ca_wq, ca_bq, nullptr, q, MQ, DD, DD, 0);
    gemm_mma<<<gk, blk>>>(cross, ca_wk, ca_bk, nullptr, k, MK, DD, DD, 0);
    gemm_mma<<<gk, blk>>>(cross, ca_wv, ca_bv, nullptr, v, MK, DD, DD, 0);
    attn_mma<<<ga, 128, ATT_SMEM>>>(q, k, v, c, NQ, NK);
    gemm_mma<<<gq, blk>>>(c, ca_wo, ca_bo, nullptr, xc, MQ, DD, DD, 0);

    // ---- LN1 + self-attention ----
    layernorm_k<<<MQ, 128>>>(xc, ln1_g, ln1_b, xn);
    gemm_mma<<<gq, blk>>>(xn, sa_wq, sa_bq, nullptr, q, MQ, DD, DD, 0);
    gemm_mma<<<gq, blk>>>(xn, sa_wk, sa_bk, nullptr, k, MQ, DD, DD, 0);
    gemm_mma<<<gq, blk>>>(xn, sa_wv, sa_bv, nullptr, v, MQ, DD, DD, 0);
    attn_mma<<<ga, 128, ATT_SMEM>>>(q, k, v, c, NQ, NQ);
    gemm_mma<<<gq, blk>>>(c, sa_wo, sa_bo, xc, y, MQ, DD, DD, 2);   // y = xc + xs

    // ---- LN2 + MLP + residual ----
    layernorm_k<<<MQ, 128>>>(y, ln2_g, ln2_b, xn);
    gemm_mma<<<gh, blk>>>(xn, mlp_w1, mlp_b1, nullptr, h1, MQ, HID, DD, 1);  // GELU
    gemm_mma<<<gq, blk>>>(h1, mlp_w2, mlp_b2, y, out, MQ, DD, HID, 2);       // + y
}

// round 10
// speedup vs baseline: 4.3026x; 1.1539x over previous
#include <cuda_runtime.h>
#include <cuda_bf16.h>
#include <math.h>
#include <stdint.h>

// ---------------------------------------------------------------------------
// Problem constants
// ---------------------------------------------------------------------------
#define BB   2
#define NQ   2048
#define NK   4096
#define DD   512
#define HH   8
#define HID  2048
#define MQ   (BB*NQ)   // 4096
#define MK   (BB*NK)   // 8192

// ---------------------------------------------------------------------------
// Scratch (static device globals; no runtime allocation)
// ---------------------------------------------------------------------------
__device__ __align__(16) float g_q [MQ*DD];
__device__ __align__(16) float g_k [MK*DD];
__device__ __align__(16) float g_v [MK*DD];
__device__ __align__(16) float g_c [MQ*DD];
__device__ __align__(16) float g_xc[MQ*DD];
__device__ __align__(16) float g_xn[MQ*DD];
__device__ __align__(16) float g_y [MQ*DD];
__device__ __align__(16) float g_h1[MQ*HID];

// ---------------------------------------------------------------------------
// mma.sync helpers (portable tensor-core path; works on plain sm_103 target)
// ---------------------------------------------------------------------------
__device__ __forceinline__ uint32_t tf32r(float x) {
    uint32_t u;
    asm("cvt.rna.tf32.f32 %0, %1;" : "=r"(u) : "f"(x));
    return u;
}

__device__ __forceinline__ void mma_tf32(float c[4],
                                         uint32_t a0, uint32_t a1,
                                         uint32_t a2, uint32_t a3,
                                         uint32_t b0, uint32_t b1)
{
    asm volatile(
        "mma.sync.aligned.m16n8k8.row.col.f32.tf32.tf32.f32 "
        "{%0,%1,%2,%3}, {%4,%5,%6,%7}, {%8,%9}, {%0,%1,%2,%3};"
        : "+f"(c[0]), "+f"(c[1]), "+f"(c[2]), "+f"(c[3])
        : "r"(a0), "r"(a1), "r"(a2), "r"(a3), "r"(b0), "r"(b1));
}

__device__ __forceinline__ uint32_t fbits(float x) { return __float_as_uint(x); }

// ---------------------------------------------------------------------------
// tf32 tensor-core GEMM: C[M,N] = A[M,K] @ W[K,N] + bias, epilogue
//   epi = 0: none   epi = 1: GELU(erf)   epi = 2: + Res
// CTA tile 128x128, BK=32. 256 threads = 8 warps as 4(m) x 2(n),
// warp tile 32x64 = 2 m-tiles x 8 n-tiles of m16n8k8.
// A smem stride 36 (bank-free: 4g+t), W smem stride 136 (bank-free: 8t+g).
// (unchanged from R6 — verified working)
// ---------------------------------------------------------------------------
__global__ void __launch_bounds__(256)
gemm_mma(const float* __restrict__ A, const float* __restrict__ W,
         const float* __restrict__ bias, const float* __restrict__ Res,
         float* __restrict__ C, int M, int N, int K, int epi)
{
    __shared__ float As[128 * 36];
    __shared__ float Ws[32 * 136];

    const int tid = threadIdx.x;
    const int wid = tid >> 5, lane = tid & 31;
    const int g = lane >> 2, t = lane & 3;
    const int wm = wid >> 1, wn = wid & 1;
    const int m0 = blockIdx.y * 128, n0 = blockIdx.x * 128;

    float acc[2][8][4];
    #pragma unroll
    for (int mt = 0; mt < 2; ++mt)
        #pragma unroll
        for (int nt = 0; nt < 8; ++nt)
            #pragma unroll
            for (int j = 0; j < 4; ++j) acc[mt][nt][j] = 0.f;

    for (int kc = 0; kc < K; kc += 32) {
        #pragma unroll
        for (int it = 0; it < 4; ++it) {
            int idx = tid + it * 256;
            int r = idx >> 3, c4 = idx & 7;
            float4 v = *(const float4*)(A + (size_t)(m0 + r) * K + kc + c4 * 4);
            float* p = &As[r * 36 + c4 * 4];
            p[0] = __uint_as_float(tf32r(v.x));
            p[1] = __uint_as_float(tf32r(v.y));
            p[2] = __uint_as_float(tf32r(v.z));
            p[3] = __uint_as_float(tf32r(v.w));
        }
        #pragma unroll
        for (int it = 0; it < 4; ++it) {
            int idx = tid + it * 256;
            int r = idx >> 5, c4 = idx & 31;
            float4 v = *(const float4*)(W + (size_t)(kc + r) * N + n0 + c4 * 4);
            float* p = &Ws[r * 136 + c4 * 4];
            p[0] = __uint_as_float(tf32r(v.x));
            p[1] = __uint_as_float(tf32r(v.y));
            p[2] = __uint_as_float(tf32r(v.z));
            p[3] = __uint_as_float(tf32r(v.w));
        }
        __syncthreads();

        #pragma unroll
        for (int kk = 0; kk < 4; ++kk) {
            const int k0 = kk * 8;
            uint32_t a[2][4];
            #pragma unroll
            for (int mt = 0; mt < 2; ++mt) {
                const int rb = wm * 32 + mt * 16;
                a[mt][0] = fbits(As[(rb + g    ) * 36 + k0 + t    ]);
                a[mt][1] = fbits(As[(rb + g + 8) * 36 + k0 + t    ]);
                a[mt][2] = fbits(As[(rb + g    ) * 36 + k0 + t + 4]);
                a[mt][3] = fbits(As[(rb + g + 8) * 36 + k0 + t + 4]);
            }
            #pragma unroll
            for (int nt = 0; nt < 8; ++nt) {
                uint32_t b0 = fbits(Ws[(k0 + t    ) * 136 + wn * 64 + nt * 8 + g]);
                uint32_t b1 = fbits(Ws[(k0 + t + 4) * 136 + wn * 64 + nt * 8 + g]);
                mma_tf32(acc[0][nt], a[0][0], a[0][1], a[0][2], a[0][3], b0, b1);
                mma_tf32(acc[1][nt], a[1][0], a[1][1], a[1][2], a[1][3], b0, b1);
            }
        }
        __syncthreads();
    }

    #pragma unroll
    for (int mt = 0; mt < 2; ++mt) {
        #pragma unroll
        for (int nt = 0; nt < 8; ++nt) {
            const int row = m0 + wm * 32 + mt * 16 + g;
            const int col = n0 + wn * 64 + nt * 8 + 2 * t;
            const float bs0 = __ldg(&bias[col]);
            const float bs1 = __ldg(&bias[col + 1]);
            float r0 = acc[mt][nt][0] + bs0;
            float r1 = acc[mt][nt][1] + bs1;
            float r2 = acc[mt][nt][2] + bs0;
            float r3 = acc[mt][nt][3] + bs1;
            if (epi == 1) {
                r0 = 0.5f * r0 * (1.f + erff(r0 * 0.70710678118654752f));
                r1 = 0.5f * r1 * (1.f + erff(r1 * 0.70710678118654752f));
                r2 = 0.5f * r2 * (1.f + erff(r2 * 0.70710678118654752f));
                r3 = 0.5f * r3 * (1.f + erff(r3 * 0.70710678118654752f));
            } else if (epi == 2) {
                float2 u = *(const float2*)&Res[(size_t)row * N + col];
                float2 w = *(const float2*)&Res[(size_t)(row + 8) * N + col];
                r0 += u.x; r1 += u.y; r2 += w.x; r3 += w.y;
            }
            float2 o0 = {r0, r1}, o1 = {r2, r3};
            *(float2*)&C[(size_t)row * N + col] = o0;
            *(float2*)&C[(size_t)(row + 8) * N + col] = o1;
        }
    }
}

// ---------------------------------------------------------------------------
// Flash attention, tf32 mma, v2: CTA tile = 128 queries x 64 keys.
// 128 threads = 4 warps; each warp owns 32 query rows = 2 m-tiles x 8 n-tiles.
// B-fragment reuse across 2 m-tiles halves smem bytes/FLOP vs R6.
// Smem (dynamic, 88KB): Qs[128][68] | KV (K view [64][68], V view [64][72])
//                       | Ps[128][68]. All strides bank-conflict-free.
// ---------------------------------------------------------------------------
#define ATT_SMEM ((128*68 + 64*72 + 128*68) * 4)

__global__ void __launch_bounds__(128)
attn_mma(const float* __restrict__ Qg, const float* __restrict__ Kg,
         const float* __restrict__ Vg, float* __restrict__ Og,
         int Nq, int Nk)
{
    extern __shared__ float sm[];
    float* Qs = sm;                          // [128][68]
    float* KV = sm + 128 * 68;               // K:[64][68]  V:[64][72]
    float* Ps = sm + 128 * 68 + 64 * 72;     // [128][68]

    const int tid = threadIdx.x;
    const int wid = tid >> 5, lane = tid & 31;
    const int g = lane >> 2, t = lane & 3;
    const int b = blockIdx.z, h = blockIdx.y;
    const int q0 = blockIdx.x * 128;

    const float* qbase = Qg + (size_t)(b * Nq + q0) * DD + h * 64;
    const float* kbase = Kg + (size_t)b * Nk * DD + h * 64;
    const float* vbase = Vg + (size_t)b * Nk * DD + h * 64;

    // Q tile (128 rows), pre-scaled by d^-0.5 = 0.125 (exact), tf32-rounded
    #pragma unroll
    for (int it = 0; it < 16; ++it) {
        int idx = tid + it * 128;
        int r = idx >> 4, c4 = idx & 15;
        float4 v = *(const float4*)(qbase + (size_t)r * DD + c4 * 4);
        float* p = &Qs[r * 68 + c4 * 4];
        p[0] = __uint_as_float(tf32r(v.x * 0.125f));
        p[1] = __uint_as_float(tf32r(v.y * 0.125f));
        p[2] = __uint_as_float(tf32r(v.z * 0.125f));
        p[3] = __uint_as_float(tf32r(v.w * 0.125f));
    }

    // Per-thread rows: mt in {0,1}, half in {0,1}:
    //   row(mt, half) = wid*32 + mt*16 + half*8 + g
    float m_i[4], l_i[4];
    float o[2][8][4];
    #pragma unroll
    for (int i = 0; i < 4; ++i) { m_i[i] = -1e30f; l_i[i] = 0.f; }
    #pragma unroll
    for (int mt = 0; mt < 2; ++mt)
        #pragma unroll
        for (int nt = 0; nt < 8; ++nt)
            #pragma unroll
            for (int j = 0; j < 4; ++j) o[mt][nt][j] = 0.f;

    const int rw = wid * 32;     // warp's row base
    const int nT = Nk >> 6;

    for (int kb = 0; kb < nT; ++kb) {
        __syncthreads();   // prior P@V reads of KV done; (iter 0: Q store visible anyway after next sync)

        // K tile (natural [key][d]), stride 68
        const float* kt = kbase + (size_t)(kb * 64) * DD;
        #pragma unroll
        for (int it = 0; it < 8; ++it) {
            int idx = tid + it * 128;
            int r = idx >> 4, c4 = idx & 15;
            float4 v = *(const float4*)(kt + (size_t)r * DD + c4 * 4);
            float* p = &KV[r * 68 + c4 * 4];
            p[0] = __uint_as_float(tf32r(v.x));
            p[1] = __uint_as_float(tf32r(v.y));
            p[2] = __uint_as_float(tf32r(v.z));
            p[3] = __uint_as_float(tf32r(v.w));
        }
        __syncthreads();

        // S = Q @ K^T  (warp: 32 rows x 64 keys, 2 m-tiles x 8 n-tiles)
        float s[2][8][4];
        #pragma unroll
        for (int mt = 0; mt < 2; ++mt)
            #pragma unroll
            for (int nt = 0; nt < 8; ++nt)
                #pragma unroll
                for (int j = 0; j < 4; ++j) s[mt][nt][j] = 0.f;

        #pragma unroll
        for (int kk = 0; kk < 8; ++kk) {
            const int k0 = kk * 8;
            uint32_t a[2][4];
            #pragma unroll
            for (int mt = 0; mt < 2; ++mt) {
                const int rb = rw + mt * 16;
                a[mt][0] = fbits(Qs[(rb + g    ) * 68 + k0 + t    ]);
                a[mt][1] = fbits(Qs[(rb + g + 8) * 68 + k0 + t    ]);
                a[mt][2] = fbits(Qs[(rb + g    ) * 68 + k0 + t + 4]);
                a[mt][3] = fbits(Qs[(rb + g + 8) * 68 + k0 + t + 4]);
            }
            #pragma unroll
            for (int nt = 0; nt < 8; ++nt) {
                uint32_t b0 = fbits(KV[(nt * 8 + g) * 68 + k0 + t    ]);
                uint32_t b1 = fbits(KV[(nt * 8 + g) * 68 + k0 + t + 4]);
                mma_tf32(s[0][nt], a[0][0], a[0][1], a[0][2], a[0][3], b0, b1);
                mma_tf32(s[1][nt], a[1][0], a[1][1], a[1][2], a[1][3], b0, b1);
            }
        }

        // Online softmax per (mt, half). Row spread over 4 lanes t -> xor 1,2.
        #pragma unroll
        for (int mt = 0; mt < 2; ++mt) {
            float rmax0 = -1e30f, rmax1 = -1e30f;
            #pragma unroll
            for (int nt = 0; nt < 8; ++nt) {
                rmax0 = fmaxf(rmax0, fmaxf(s[mt][nt][0], s[mt][nt][1]));
                rmax1 = fmaxf(rmax1, fmaxf(s[mt][nt][2], s[mt][nt][3]));
            }
            rmax0 = fmaxf(rmax0, __shfl_xor_sync(0xffffffffu, rmax0, 1));
            rmax0 = fmaxf(rmax0, __shfl_xor_sync(0xffffffffu, rmax0, 2));
            rmax1 = fmaxf(rmax1, __shfl_xor_sync(0xffffffffu, rmax1, 1));
            rmax1 = fmaxf(rmax1, __shfl_xor_sync(0xffffffffu, rmax1, 2));

            const float mn0 = fmaxf(m_i[mt * 2 + 0], rmax0);
            const float mn1 = fmaxf(m_i[mt * 2 + 1], rmax1);
            const float corr0 = __expf(m_i[mt * 2 + 0] - mn0);
            const float corr1 = __expf(m_i[mt * 2 + 1] - mn1);

            const int r0 = rw + mt * 16 + g;
            float rs0 = 0.f, rs1 = 0.f;
            #pragma unroll
            for (int nt = 0; nt < 8; ++nt) {
                float p0 = __expf(s[mt][nt][0] - mn0);
                float p1 = __expf(s[mt][nt][1] - mn0);
                float p2 = __expf(s[mt][nt][2] - mn1);
                float p3 = __expf(s[mt][nt][3] - mn1);
                rs0 += p0 + p1;
                rs1 += p2 + p3;
                const int col = nt * 8 + 2 * t;
                float2 w0 = {__uint_as_float(tf32r(p0)), __uint_as_float(tf32r(p1))};
                float2 w1 = {__uint_as_float(tf32r(p2)), __uint_as_float(tf32r(p3))};
                *(float2*)&Ps[(r0    ) * 68 + col] = w0;
                *(float2*)&Ps[(r0 + 8) * 68 + col] = w1;
            }
            rs0 += __shfl_xor_sync(0xffffffffu, rs0, 1);
            rs0 += __shfl_xor_sync(0xffffffffu, rs0, 2);
            rs1 += __shfl_xor_sync(0xffffffffu, rs1, 1);
            rs1 += __shfl_xor_sync(0xffffffffu, rs1, 2);

            l_i[mt * 2 + 0] = l_i[mt * 2 + 0] * corr0 + rs0;
            l_i[mt * 2 + 1] = l_i[mt * 2 + 1] * corr1 + rs1;
            m_i[mt * 2 + 0] = mn0;
            m_i[mt * 2 + 1] = mn1;
            #pragma unroll
            for (int nt = 0; nt < 8; ++nt) {
                o[mt][nt][0] *= corr0; o[mt][nt][1] *= corr0;
                o[mt][nt][2] *= corr1; o[mt][nt][3] *= corr1;
            }
        }
        __syncthreads();   // all warps done reading K before V overwrite

        // V tile (natural [key][d]), stride 72
        const float* vt = vbase + (size_t)(kb * 64) * DD;
        #pragma unroll
        for (int it = 0; it < 8; ++it) {
            int idx = tid + it * 128;
            int r = idx >> 4, c4 = idx & 15;
            float4 v = *(const float4*)(vt + (size_t)r * DD + c4 * 4);
            float* p = &KV[r * 72 + c4 * 4];
            p[0] = __uint_as_float(tf32r(v.x));
            p[1] = __uint_as_float(tf32r(v.y));
            p[2] = __uint_as_float(tf32r(v.z));
            p[3] = __uint_as_float(tf32r(v.w));
        }
        __syncthreads();

        // O += P @ V  (K dim = 64 keys)
        #pragma unroll
        for (int kk = 0; kk < 8; ++kk) {
            const int k0 = kk * 8;
            uint32_t a[2][4];
            #pragma unroll
            for (int mt = 0; mt < 2; ++mt) {
                const int rb = rw + mt * 16;
                a[mt][0] = fbits(Ps[(rb + g    ) * 68 + k0 + t    ]);
                a[mt][1] = fbits(Ps[(rb + g + 8) * 68 + k0 + t    ]);
                a[mt][2] = fbits(Ps[(rb + g    ) * 68 + k0 + t + 4]);
                a[mt][3] = fbits(Ps[(rb + g + 8) * 68 + k0 + t + 4]);
            }
            #pragma unroll
            for (int nt = 0; nt < 8; ++nt) {
                uint32_t b0 = fbits(KV[(k0 + t    ) * 72 + nt * 8 + g]);
                uint32_t b1 = fbits(KV[(k0 + t + 4) * 72 + nt * 8 + g]);
                mma_tf32(o[0][nt], a[0][0], a[0][1], a[0][2], a[0][3], b0, b1);
                mma_tf32(o[1][nt], a[1][0], a[1][1], a[1][2], a[1][3], b0, b1);
            }
        }
    }

    // Normalize + write
    #pragma unroll
    for (int mt = 0; mt < 2; ++mt) {
        const float inv0 = 1.0f / l_i[mt * 2 + 0];
        const float inv1 = 1.0f / l_i[mt * 2 + 1];
        const int r0g = b * Nq + q0 + rw + mt * 16 + g;
        #pragma unroll
        for (int nt = 0; nt < 8; ++nt) {
            const int col = h * 64 + nt * 8 + 2 * t;
            float2 w0 = {o[mt][nt][0] * inv0, o[mt][nt][1] * inv0};
            float2 w1 = {o[mt][nt][2] * inv1, o[mt][nt][3] * inv1};
            *(float2*)&Og[(size_t)r0g * DD + col] = w0;
            *(float2*)&Og[(size_t)(r0g + 8) * DD + col] = w1;
        }
    }
}

// ---------------------------------------------------------------------------
// LayerNorm over last dim (512), biased variance, eps=1e-5.
// ---------------------------------------------------------------------------
__global__ void __launch_bounds__(128)
layernorm_k(const float* __restrict__ X, const float* __restrict__ gam,
            const float* __restrict__ bet, float* __restrict__ Y)
{
    __shared__ float red[8];
    const int row = blockIdx.x, tid = threadIdx.x;
    float4 v = *(const float4*)&X[(size_t)row * DD + tid * 4];
    float s  = v.x + v.y + v.z + v.w;
    float ss = v.x * v.x + v.y * v.y + v.z * v.z + v.w * v.w;
    #pragma unroll
    for (int o = 16; o; o >>= 1) {
        s  += __shfl_xor_sync(0xffffffffu, s, o);
        ss += __shfl_xor_sync(0xffffffffu, ss, o);
    }
    if ((tid & 31) == 0) { red[tid >> 5] = s; red[4 + (tid >> 5)] = ss; }
    __syncthreads();
    s  = red[0] + red[1] + red[2] + red[3];
    ss = red[4] + red[5] + red[6] + red[7];
    float mean = s * (1.f / 512.f);
    float var  = ss * (1.f / 512.f) - mean * mean;
    float rstd = rsqrtf(var + 1e-5f);
    float4 g4 = *(const float4*)&gam[tid * 4];
    float4 b4 = *(const float4*)&bet[tid * 4];
    float4 o;
    o.x = (v.x - mean) * rstd * g4.x + b4.x;
    o.y = (v.y - mean) * rstd * g4.y + b4.y;
    o.z = (v.z - mean) * rstd * g4.z + b4.z;
    o.w = (v.w - mean) * rstd * g4.w + b4.w;
    *(float4*)&Y[(size_t)row * DD + tid * 4] = o;
}

// ---------------------------------------------------------------------------
// Host orchestration (graph-capturable: kernel launches only)
// ---------------------------------------------------------------------------
extern "C" void kernel_launch(void* const* d_in, const int* in_sizes, int n_in,
                              void* d_out, int out_size)
{
    const float* x      = (const float*)d_in[0];
    const float* cross  = (const float*)d_in[1];
    const float* ca_wq  = (const float*)d_in[2];
    const float* ca_bq  = (const float*)d_in[3];
    const float* ca_wk  = (const float*)d_in[4];
    const float* ca_bk  = (const float*)d_in[5];
    const float* ca_wv  = (const float*)d_in[6];
    const float* ca_bv  = (const float*)d_in[7];
    const float* ca_wo  = (const float*)d_in[8];
    const float* ca_bo  = (const float*)d_in[9];
    const float* sa_wq  = (const float*)d_in[10];
    const float* sa_bq  = (const float*)d_in[11];
    const float* sa_wk  = (const float*)d_in[12];
    const float* sa_bk  = (const float*)d_in[13];
    const float* sa_wv  = (const float*)d_in[14];
    const float* sa_bv  = (const float*)d_in[15];
    const float* sa_wo  = (const float*)d_in[16];
    const float* sa_bo  = (const float*)d_in[17];
    const float* ln1_g  = (const float*)d_in[18];
    const float* ln1_b  = (const float*)d_in[19];
    const float* ln2_g  = (const float*)d_in[20];
    const float* ln2_b  = (const float*)d_in[21];
    const float* mlp_w1 = (const float*)d_in[22];
    const float* mlp_b1 = (const float*)d_in[23];
    const float* mlp_w2 = (const float*)d_in[24];
    const float* mlp_b2 = (const float*)d_in[25];
    float* out = (float*)d_out;

    float *q, *k, *v, *c, *xc, *xn, *y, *h1;
    cudaGetSymbolAddress((void**)&q,  g_q);
    cudaGetSymbolAddress((void**)&k,  g_k);
    cudaGetSymbolAddress((void**)&v,  g_v);
    cudaGetSymbolAddress((void**)&c,  g_c);
    cudaGetSymbolAddress((void**)&xc, g_xc);
    cudaGetSymbolAddress((void**)&xn, g_xn);
    cudaGetSymbolAddress((void**)&y,  g_y);
    cudaGetSymbolAddress((void**)&h1, g_h1);

    cudaFuncSetAttribute(attn_mma, cudaFuncAttributeMaxDynamicSharedMemorySize,
                         ATT_SMEM);

    const dim3 blk(256);
    const dim3 gq(DD / 128, MQ / 128);    // 4 x 32
    const dim3 gk(DD / 128, MK / 128);    // 4 x 64
    const dim3 gh(HID / 128, MQ / 128);   // 16 x 32
    const dim3 ga(NQ / 128, HH, BB);      // 16 x 8 x 2

    // ---- cross-attention ----
    gemm_mma<<<gq, blk>>>(x,     ca_wq, ca_bq, nullptr, q, MQ, DD, DD, 0);
    gemm_mma<<<gk, blk>>>(cross, ca_wk, ca_bk, nullptr, k, MK, DD, DD, 0);
    gemm_mma<<<gk, blk>>>(cross, ca_wv, ca_bv, nullptr, v, MK, DD, DD, 0);
    attn_mma<<<ga, 128, ATT_SMEM>>>(q, k, v, c, NQ, NK);
    gemm_mma<<<gq, blk>>>(c, ca_wo, ca_bo, nullptr, xc, MQ, DD, DD, 0);

    // ---- LN1 + self-attention ----
    layernorm_k<<<MQ, 128>>>(xc, ln1_g, ln1_b, xn);
    gemm_mma<<<gq, blk>>>(xn, sa_wq, sa_bq, nullptr, q, MQ, DD, DD, 0);
    gemm_mma<<<gq, blk>>>(xn, sa_wk, sa_bk, nullptr, k, MQ, DD, DD, 0);
    gemm_mma<<<gq, blk>>>(xn, sa_wv, sa_bv, nullptr, v, MQ, DD, DD, 0);
    attn_mma<<<ga, 128, ATT_SMEM>>>(q, k, v, c, NQ, NQ);
    gemm_mma<<<gq, blk>>>(c, sa_wo, sa_bo, xc, y, MQ, DD, DD, 2);   // y = xc + xs

    // ---- LN2 + MLP + residual ----
    layernorm_k<<<MQ, 128>>>(y, ln2_g, ln2_b, xn);
    gemm_mma<<<gh, blk>>>(xn, mlp_w1, mlp_b1, nullptr, h1, MQ, HID, DD, 1);  // GELU
    gemm_mma<<<gq, blk>>>(h1, mlp_w2, mlp_b2, y, out, MQ, DD, HID, 2);       // + y
}

// round 11
// speedup vs baseline: 6.5069x; 1.5123x over previous
#include <cuda_runtime.h>
#include <cuda_fp16.h>
#include <math.h>
#include <stdint.h>

// ---------------------------------------------------------------------------
// Problem constants
// ---------------------------------------------------------------------------
#define BB   2
#define NQ   2048
#define NK   4096
#define DD   512
#define HH   8
#define HID  2048
#define MQ   (BB*NQ)   // 4096
#define MK   (BB*NK)   // 8192

// ---------------------------------------------------------------------------
// Scratch (static device globals; no runtime allocation)
// ---------------------------------------------------------------------------
__device__ __align__(16) float g_q [MQ*DD];
__device__ __align__(16) float g_k [MK*DD];
__device__ __align__(16) float g_v [MK*DD];
__device__ __align__(16) float g_c [MQ*DD];
__device__ __align__(16) float g_xc[MQ*DD];
__device__ __align__(16) float g_xn[MQ*DD];
__device__ __align__(16) float g_y [MQ*DD];
__device__ __align__(16) float g_h1[MQ*HID];

// ---------------------------------------------------------------------------
// fp16 mma.sync + ldmatrix helpers (sm_75+/sm_80+, valid on plain sm_103)
// ---------------------------------------------------------------------------
__device__ __forceinline__ uint32_t cvta_smem(const void* p) {
    uint32_t a;
    asm("{ .reg .u64 t; cvta.to.shared.u64 t, %1; cvt.u32.u64 %0, t; }"
        : "=r"(a) : "l"(p));
    return a;
}

__device__ __forceinline__ void ldsm4(uint32_t r[4], uint32_t a) {
    asm volatile("ldmatrix.sync.aligned.m8n8.x4.shared.b16 {%0,%1,%2,%3}, [%4];"
        : "=r"(r[0]), "=r"(r[1]), "=r"(r[2]), "=r"(r[3]) : "r"(a));
}
__device__ __forceinline__ void ldsm4t(uint32_t r[4], uint32_t a) {
    asm volatile("ldmatrix.sync.aligned.m8n8.x4.trans.shared.b16 {%0,%1,%2,%3}, [%4];"
        : "=r"(r[0]), "=r"(r[1]), "=r"(r[2]), "=r"(r[3]) : "r"(a));
}

__device__ __forceinline__ void mma_f16(float c[4],
                                        uint32_t a0, uint32_t a1,
                                        uint32_t a2, uint32_t a3,
                                        uint32_t b0, uint32_t b1)
{
    asm volatile(
        "mma.sync.aligned.m16n8k16.row.col.f32.f16.f16.f32 "
        "{%0,%1,%2,%3}, {%4,%5,%6,%7}, {%8,%9}, {%0,%1,%2,%3};"
        : "+f"(c[0]), "+f"(c[1]), "+f"(c[2]), "+f"(c[3])
        : "r"(a0), "r"(a1), "r"(a2), "r"(a3), "r"(b0), "r"(b1));
}

// pack two fp32 -> half2 (RN, unbiased); .x (=lo half) is first arg
__device__ __forceinline__ uint32_t packh2(float lo, float hi) {
    __half2 h = __floats2half2_rn(lo, hi);
    uint32_t u;
    *(__half2*)&u = h;
    return u;
}

// ---------------------------------------------------------------------------
// fp16 tensor-core GEMM: C[M,N] = A[M,K] @ W[K,N] + bias, epilogue
//   epi = 0: none   epi = 1: GELU(erf)   epi = 2: + Res
// CTA 128x128, BK=64. 256 threads = 8 warps (4m x 2n), warp 32x64,
// mt=2 x nt=8 tiles of m16n8k16 (4 k-steps per chunk).
// As[128][72] halves (row stride 144B), Ws[64][136] halves (272B) --
// both ldmatrix phase-conflict-free (stride mod 128B = 16).
// W consumed via ldmatrix.trans (no weight transpose anywhere).
// ---------------------------------------------------------------------------
#define GA_STR 72
#define GW_STR 136

__global__ void __launch_bounds__(256, 2)
gemm_mma(const float* __restrict__ A, const float* __restrict__ W,
         const float* __restrict__ bias, const float* __restrict__ Res,
         float* __restrict__ C, int M, int N, int K, int epi)
{
    __shared__ uint16_t As[128 * GA_STR];
    __shared__ uint16_t Ws[64 * GW_STR];
    const uint32_t as_b = cvta_smem(As);
    const uint32_t ws_b = cvta_smem(Ws);

    const int tid = threadIdx.x;
    const int wid = tid >> 5, lane = tid & 31;
    const int g = lane >> 2, t = lane & 3;
    const int wm = wid >> 1, wn = wid & 1;
    const int m0 = blockIdx.y * 128, n0 = blockIdx.x * 128;

    // ldmatrix lane->address components (computed once)
    const int l8  = lane & 7;
    const int s3  = (lane >> 3) & 1;
    const int s4  = (lane >> 4) & 1;

    float acc[2][8][4];
    #pragma unroll
    for (int mt = 0; mt < 2; ++mt)
        #pragma unroll
        for (int nt = 0; nt < 8; ++nt)
            #pragma unroll
            for (int j = 0; j < 4; ++j) acc[mt][nt][j] = 0.f;

    for (int kc = 0; kc < K; kc += 64) {
        // A: 128 rows x 64 floats -> fp16, K-major coalesced
        #pragma unroll
        for (int it = 0; it < 8; ++it) {
            int idx = tid + it * 256;
            int r = idx >> 4, c4 = idx & 15;
            float4 v = *(const float4*)(A + (size_t)(m0 + r) * K + kc + c4 * 4);
            uint2 u = { packh2(v.x, v.y), packh2(v.z, v.w) };
            *(uint2*)&As[r * GA_STR + c4 * 4] = u;
        }
        // W: 64 rows x 128 floats -> fp16, natural row-major
        #pragma unroll
        for (int it = 0; it < 8; ++it) {
            int idx = tid + it * 256;
            int r = idx >> 5, c4 = idx & 31;
            float4 v = *(const float4*)(W + (size_t)(kc + r) * N + n0 + c4 * 4);
            uint2 u = { packh2(v.x, v.y), packh2(v.z, v.w) };
            *(uint2*)&Ws[r * GW_STR + c4 * 4] = u;
        }
        __syncthreads();

        #pragma unroll
        for (int kk = 0; kk < 4; ++kk) {
            const int k0 = kk * 16;
            uint32_t a[2][4];
            #pragma unroll
            for (int mt = 0; mt < 2; ++mt) {
                const int row = wm * 32 + mt * 16 + l8 + s3 * 8;
                const int col = k0 + s4 * 8;
                ldsm4(a[mt], as_b + (uint32_t)(row * GA_STR + col) * 2);
            }
            #pragma unroll
            for (int ntp = 0; ntp < 4; ++ntp) {
                const int row = k0 + l8 + s3 * 8;
                const int col = wn * 64 + ntp * 16 + s4 * 8;
                uint32_t b[4];
                ldsm4t(b, ws_b + (uint32_t)(row * GW_STR + col) * 2);
                mma_f16(acc[0][2*ntp  ], a[0][0], a[0][1], a[0][2], a[0][3], b[0], b[1]);
                mma_f16(acc[1][2*ntp  ], a[1][0], a[1][1], a[1][2], a[1][3], b[0], b[1]);
                mma_f16(acc[0][2*ntp+1], a[0][0], a[0][1], a[0][2], a[0][3], b[2], b[3]);
                mma_f16(acc[1][2*ntp+1], a[1][0], a[1][1], a[1][2], a[1][3], b[2], b[3]);
            }
        }
        __syncthreads();
    }

    // Epilogue: c0,c1 -> (row, col..col+1); c2,c3 -> (row+8, same cols)
    #pragma unroll
    for (int mt = 0; mt < 2; ++mt) {
        #pragma unroll
        for (int nt = 0; nt < 8; ++nt) {
            const int row = m0 + wm * 32 + mt * 16 + g;
            const int col = n0 + wn * 64 + nt * 8 + 2 * t;
            const float bs0 = __ldg(&bias[col]);
            const float bs1 = __ldg(&bias[col + 1]);
            float r0 = acc[mt][nt][0] + bs0;
            float r1 = acc[mt][nt][1] + bs1;
            float r2 = acc[mt][nt][2] + bs0;
            float r3 = acc[mt][nt][3] + bs1;
            if (epi == 1) {
                r0 = 0.5f * r0 * (1.f + erff(r0 * 0.70710678118654752f));
                r1 = 0.5f * r1 * (1.f + erff(r1 * 0.70710678118654752f));
                r2 = 0.5f * r2 * (1.f + erff(r2 * 0.70710678118654752f));
                r3 = 0.5f * r3 * (1.f + erff(r3 * 0.70710678118654752f));
            } else if (epi == 2) {
                float2 u = *(const float2*)&Res[(size_t)row * N + col];
                float2 w = *(const float2*)&Res[(size_t)(row + 8) * N + col];
                r0 += u.x; r1 += u.y; r2 += w.x; r3 += w.y;
            }
            float2 o0 = {r0, r1}, o1 = {r2, r3};
            *(float2*)&C[(size_t)row * N + col] = o0;
            *(float2*)&C[(size_t)(row + 8) * N + col] = o1;
        }
    }
}

// ---------------------------------------------------------------------------
// Flash attention, fp16 mma. CTA = 128 queries x 64 keys, 128 threads (4 warps),
// warp = 32 query rows (mt=2) x 64 keys/dims (nt=8).
// S = Q@K^T: K consumed ldmatrix NON-trans (natural [key][d] is col-major for K^T).
// P stays IN REGISTERS: m16n8k16 accumulator (cols 2t,2t+1) packs directly into
// the fp16 A-fragment via __floats2half2_rn -- no smem round-trip, no shuffles.
// O += P@V: V natural [key][d], ldmatrix TRANS.
// Smem 36.9KB static: Qs[128][72] | Ks[64][72] | Vs[64][72] halves.
// ---------------------------------------------------------------------------
__global__ void __launch_bounds__(128, 2)
attn_mma(const float* __restrict__ Qg, const float* __restrict__ Kg,
         const float* __restrict__ Vg, float* __restrict__ Og,
         int Nq, int Nk)
{
    __shared__ uint16_t Qs[128 * 72];
    __shared__ uint16_t Ks[64 * 72];
    __shared__ uint16_t Vs[64 * 72];
    const uint32_t qs_b = cvta_smem(Qs);
    const uint32_t ks_b = cvta_smem(Ks);
    const uint32_t vs_b = cvta_smem(Vs);

    const int tid = threadIdx.x;
    const int wid = tid >> 5, lane = tid & 31;
    const int g = lane >> 2, t = lane & 3;
    const int l8 = lane & 7;
    const int s3 = (lane >> 3) & 1;
    const int s4 = (lane >> 4) & 1;
    const int b = blockIdx.z, h = blockIdx.y;
    const int q0 = blockIdx.x * 128;

    const float* qbase = Qg + (size_t)(b * Nq + q0) * DD + h * 64;
    const float* kbase = Kg + (size_t)b * Nk * DD + h * 64;
    const float* vbase = Vg + (size_t)b * Nk * DD + h * 64;

    // Q tile (128 x 64), pre-scaled by d^-0.5 = 0.125 (exact), fp16 RN
    #pragma unroll
    for (int it = 0; it < 16; ++it) {
        int idx = tid + it * 128;
        int r = idx >> 4, c4 = idx & 15;
        float4 v = *(const float4*)(qbase + (size_t)r * DD + c4 * 4);
        uint2 u = { packh2(v.x * 0.125f, v.y * 0.125f),
                    packh2(v.z * 0.125f, v.w * 0.125f) };
        *(uint2*)&Qs[r * 72 + c4 * 4] = u;
    }

    float m_i[4], l_i[4];
    float o[2][8][4];
    #pragma unroll
    for (int i = 0; i < 4; ++i) { m_i[i] = -1e30f; l_i[i] = 0.f; }
    #pragma unroll
    for (int mt = 0; mt < 2; ++mt)
        #pragma unroll
        for (int nt = 0; nt < 8; ++nt)
            #pragma unroll
            for (int j = 0; j < 4; ++j) o[mt][nt][j] = 0.f;

    const int rw = wid * 32;
    const int nT = Nk >> 6;

    for (int kb = 0; kb < nT; ++kb) {
        __syncthreads();   // prior MMA reads of Ks/Vs done (iter 0: orders Qs too)

        // K and V tiles (64 x 64 each), natural [key][d], fp16
        const float* kt = kbase + (size_t)(kb * 64) * DD;
        const float* vt = vbase + (size_t)(kb * 64) * DD;
        #pragma unroll
        for (int it = 0; it < 8; ++it) {
            int idx = tid + it * 128;
            int r = idx >> 4, c4 = idx & 15;
            float4 kv = *(const float4*)(kt + (size_t)r * DD + c4 * 4);
            float4 vv = *(const float4*)(vt + (size_t)r * DD + c4 * 4);
            uint2 uk = { packh2(kv.x, kv.y), packh2(kv.z, kv.w) };
            uint2 uv = { packh2(vv.x, vv.y), packh2(vv.z, vv.w) };
            *(uint2*)&Ks[r * 72 + c4 * 4] = uk;
            *(uint2*)&Vs[r * 72 + c4 * 4] = uv;
        }
        __syncthreads();

        // S = Q @ K^T  (warp: 32 rows x 64 keys)
        float s[2][8][4];
        #pragma unroll
        for (int mt = 0; mt < 2; ++mt)
            #pragma unroll
            for (int nt = 0; nt < 8; ++nt)
                #pragma unroll
                for (int j = 0; j < 4; ++j) s[mt][nt][j] = 0.f;

        #pragma unroll
        for (int kk = 0; kk < 4; ++kk) {
            const int k0 = kk * 16;
            uint32_t a[2][4];
            #pragma unroll
            for (int mt = 0; mt < 2; ++mt) {
                const int row = rw + mt * 16 + l8 + s3 * 8;
                const int col = k0 + s4 * 8;
                ldsm4(a[mt], qs_b + (uint32_t)(row * 72 + col) * 2);
            }
            #pragma unroll
            for (int ntp = 0; ntp < 4; ++ntp) {
                // non-trans: m0 = keys nb+l8 x d k0 (b0 of nt), m1 = same keys d k0+8 (b1),
                // m2/m3 = keys nb+8+l8 (nt+1)
                const int row = ntp * 16 + l8 + s4 * 8;
                const int col = k0 + s3 * 8;
                uint32_t bf[4];
                ldsm4(bf, ks_b + (uint32_t)(row * 72 + col) * 2);
                mma_f16(s[0][2*ntp  ], a[0][0], a[0][1], a[0][2], a[0][3], bf[0], bf[1]);
                mma_f16(s[1][2*ntp  ], a[1][0], a[1][1], a[1][2], a[1][3], bf[0], bf[1]);
                mma_f16(s[0][2*ntp+1], a[0][0], a[0][1], a[0][2], a[0][3], bf[2], bf[3]);
                mma_f16(s[1][2*ntp+1], a[1][0], a[1][1], a[1][2], a[1][3], bf[2], bf[3]);
            }
        }

        // Online softmax + pack P directly into fp16 A-fragments
        uint32_t pa[2][4][4];
        #pragma unroll
        for (int mt = 0; mt < 2; ++mt) {
            float rmax0 = -1e30f, rmax1 = -1e30f;
            #pragma unroll
            for (int nt = 0; nt < 8; ++nt) {
                rmax0 = fmaxf(rmax0, fmaxf(s[mt][nt][0], s[mt][nt][1]));
                rmax1 = fmaxf(rmax1, fmaxf(s[mt][nt][2], s[mt][nt][3]));
            }
            rmax0 = fmaxf(rmax0, __shfl_xor_sync(0xffffffffu, rmax0, 1));
            rmax0 = fmaxf(rmax0, __shfl_xor_sync(0xffffffffu, rmax0, 2));
            rmax1 = fmaxf(rmax1, __shfl_xor_sync(0xffffffffu, rmax1, 1));
            rmax1 = fmaxf(rmax1, __shfl_xor_sync(0xffffffffu, rmax1, 2));

            const float mn0 = fmaxf(m_i[mt * 2 + 0], rmax0);
            const float mn1 = fmaxf(m_i[mt * 2 + 1], rmax1);
            const float corr0 = __expf(m_i[mt * 2 + 0] - mn0);
            const float corr1 = __expf(m_i[mt * 2 + 1] - mn1);

            float rs0 = 0.f, rs1 = 0.f;
            #pragma unroll
            for (int nt = 0; nt < 8; ++nt) {
                float p0 = __expf(s[mt][nt][0] - mn0);
                float p1 = __expf(s[mt][nt][1] - mn0);
                float p2 = __expf(s[mt][nt][2] - mn1);
                float p3 = __expf(s[mt][nt][3] - mn1);
                rs0 += p0 + p1;
                rs1 += p2 + p3;
                // S tile nt covers keys nt*8+{2t,2t+1}; A-frag for P@V k-chunk
                // kp = nt>>1: a0/a1 from even nt, a2/a3 from odd nt.
                const int kp = nt >> 1, half = (nt & 1) * 2;
                pa[mt][kp][half + 0] = packh2(p0, p1);
                pa[mt][kp][half + 1] = packh2(p2, p3);
            }
            rs0 += __shfl_xor_sync(0xffffffffu, rs0, 1);
            rs0 += __shfl_xor_sync(0xffffffffu, rs0, 2);
            rs1 += __shfl_xor_sync(0xffffffffu, rs1, 1);
            rs1 += __shfl_xor_sync(0xffffffffu, rs1, 2);

            l_i[mt * 2 + 0] = l_i[mt * 2 + 0] * corr0 + rs0;
            l_i[mt * 2 + 1] = l_i[mt * 2 + 1] * corr1 + rs1;
            m_i[mt * 2 + 0] = mn0;
            m_i[mt * 2 + 1] = mn1;
            #pragma unroll
            for (int nt = 0; nt < 8; ++nt) {
                o[mt][nt][0] *= corr0; o[mt][nt][1] *= corr0;
                o[mt][nt][2] *= corr1; o[mt][nt][3] *= corr1;
            }
        }

        // O += P @ V   (k = 64 keys, 4 chunks of 16; A-frags from registers)
        #pragma unroll
        for (int kp = 0; kp < 4; ++kp) {
            const int k0 = kp * 16;
            #pragma unroll
            for (int ntp = 0; ntp < 4; ++ntp) {
                const int row = k0 + l8 + s3 * 8;
                const int col = ntp * 16 + s4 * 8;
                uint32_t bf[4];
                ldsm4t(bf, vs_b + (uint32_t)(row * 72 + col) * 2);
                mma_f16(o[0][2*ntp  ], pa[0][kp][0], pa[0][kp][1], pa[0][kp][2], pa[0][kp][3], bf[0], bf[1]);
                mma_f16(o[1][2*ntp  ], pa[1][kp][0], pa[1][kp][1], pa[1][kp][2], pa[1][kp][3], bf[0], bf[1]);
                mma_f16(o[0][2*ntp+1], pa[0][kp][0], pa[0][kp][1], pa[0][kp][2], pa[0][kp][3], bf[2], bf[3]);
                mma_f16(o[1][2*ntp+1], pa[1][kp][0], pa[1][kp][1], pa[1][kp][2], pa[1][kp][3], bf[2], bf[3]);
            }
        }
    }

    // Normalize + write
    #pragma unroll
    for (int mt = 0; mt < 2; ++mt) {
        const float inv0 = 1.0f / l_i[mt * 2 + 0];
        const float inv1 = 1.0f / l_i[mt * 2 + 1];
        const int r0g = b * Nq + q0 + rw + mt * 16 + g;
        #pragma unroll
        for (int nt = 0; nt < 8; ++nt) {
            const int col = h * 64 + nt * 8 + 2 * t;
            float2 w0 = {o[mt][nt][0] * inv0, o[mt][nt][1] * inv0};
            float2 w1 = {o[mt][nt][2] * inv1, o[mt][nt][3] * inv1};
            *(float2*)&Og[(size_t)r0g * DD + col] = w0;
            *(float2*)&Og[(size_t)(r0g + 8) * DD + col] = w1;
        }
    }
}

// ---------------------------------------------------------------------------
// LayerNorm over last dim (512), biased variance, eps=1e-5.
// ---------------------------------------------------------------------------
__global__ void __launch_bounds__(128)
layernorm_k(const float* __restrict__ X, const float* __restrict__ gam,
            const float* __restrict__ bet, float* __restrict__ Y)
{
    __shared__ float red[8];
    const int row = blockIdx.x, tid = threadIdx.x;
    float4 v = *(const float4*)&X[(size_t)row * DD + tid * 4];
    float s  = v.x + v.y + v.z + v.w;
    float ss = v.x * v.x + v.y * v.y + v.z * v.z + v.w * v.w;
    #pragma unroll
    for (int o = 16; o; o >>= 1) {
        s  += __shfl_xor_sync(0xffffffffu, s, o);
        ss += __shfl_xor_sync(0xffffffffu, ss, o);
    }
    if ((tid & 31) == 0) { red[tid >> 5] = s; red[4 + (tid >> 5)] = ss; }
    __syncthreads();
    s  = red[0] + red[1] + red[2] + red[3];
    ss = red[4] + red[5] + red[6] + red[7];
    float mean = s * (1.f / 512.f);
    float var  = ss * (1.f / 512.f) - mean * mean;
    float rstd = rsqrtf(var + 1e-5f);
    float4 g4 = *(const float4*)&gam[tid * 4];
    float4 b4 = *(const float4*)&bet[tid * 4];
    float4 o;
    o.x = (v.x - mean) * rstd * g4.x + b4.x;
    o.y = (v.y - mean) * rstd * g4.y + b4.y;
    o.z = (v.z - mean) * rstd * g4.z + b4.z;
    o.w = (v.w - mean) * rstd * g4.w + b4.w;
    *(float4*)&Y[(size_t)row * DD + tid * 4] = o;
}

// ---------------------------------------------------------------------------
// Host orchestration (graph-capturable: kernel launches only)
// ---------------------------------------------------------------------------
extern "C" void kernel_launch(void* const* d_in, const int* in_sizes, int n_in,
                              void* d_out, int out_size)
{
    const float* x      = (const float*)d_in[0];
    const float* cross  = (const float*)d_in[1];
    const float* ca_wq  = (const float*)d_in[2];
    const float* ca_bq  = (const float*)d_in[3];
    const float* ca_wk  = (const float*)d_in[4];
    const float* ca_bk  = (const float*)d_in[5];
    const float* ca_wv  = (const float*)d_in[6];
    const float* ca_bv  = (const float*)d_in[7];
    const float* ca_wo  = (const float*)d_in[8];
    const float* ca_bo  = (const float*)d_in[9];
    const float* sa_wq  = (const float*)d_in[10];
    const float* sa_bq  = (const float*)d_in[11];
    const float* sa_wk  = (const float*)d_in[12];
    const float* sa_bk  = (const float*)d_in[13];
    const float* sa_wv  = (const float*)d_in[14];
    const float* sa_bv  = (const float*)d_in[15];
    const float* sa_wo  = (const float*)d_in[16];
    const float* sa_bo  = (const float*)d_in[17];
    const float* ln1_g  = (const float*)d_in[18];
    const float* ln1_b  = (const float*)d_in[19];
    const float* ln2_g  = (const float*)d_in[20];
    const float* ln2_b  = (const float*)d_in[21];
    const float* mlp_w1 = (const float*)d_in[22];
    const float* mlp_b1 = (const float*)d_in[23];
    const float* mlp_w2 = (const float*)d_in[24];
    const float* mlp_b2 = (const float*)d_in[25];
    float* out = (float*)d_out;

    float *q, *k, *v, *c, *xc, *xn, *y, *h1;
    cudaGetSymbolAddress((void**)&q,  g_q);
    cudaGetSymbolAddress((void**)&k,  g_k);
    cudaGetSymbolAddress((void**)&v,  g_v);
    cudaGetSymbolAddress((void**)&c,  g_c);
    cudaGetSymbolAddress((void**)&xc, g_xc);
    cudaGetSymbolAddress((void**)&xn, g_xn);
    cudaGetSymbolAddress((void**)&y,  g_y);
    cudaGetSymbolAddress((void**)&h1, g_h1);

    const dim3 blk(256);
    const dim3 gq(DD / 128, MQ / 128);    // 4 x 32
    const dim3 gk(DD / 128, MK / 128);    // 4 x 64
    const dim3 gh(HID / 128, MQ / 128);   // 16 x 32
    const dim3 ga(NQ / 128, HH, BB);      // 16 x 8 x 2

    // ---- cross-attention ----
    gemm_mma<<<gq, blk>>>(x,     ca_wq, ca_bq, nullptr, q, MQ, DD, DD, 0);
    gemm_mma<<<gk, blk>>>(cross, ca_wk, ca_bk, nullptr, k, MK, DD, DD, 0);
    gemm_mma<<<gk, blk>>>(cross, ca_wv, ca_bv, nullptr, v, MK, DD, DD, 0);
    attn_mma<<<ga, 128>>>(q, k, v, c, NQ, NK);
    gemm_mma<<<gq, blk>>>(c, ca_wo, ca_bo, nullptr, xc, MQ, DD, DD, 0);

    // ---- LN1 + self-attention ----
    layernorm_k<<<MQ, 128>>>(xc, ln1_g, ln1_b, xn);
    gemm_mma<<<gq, blk>>>(xn, sa_wq, sa_bq, nullptr, q, MQ, DD, DD, 0);
    gemm_mma<<<gq, blk>>>(xn, sa_wk, sa_bk, nullptr, k, MQ, DD, DD, 0);
    gemm_mma<<<gq, blk>>>(xn, sa_wv, sa_bv, nullptr, v, MQ, DD, DD, 0);
    attn_mma<<<ga, 128>>>(q, k, v, c, NQ, NQ);
    gemm_mma<<<gq, blk>>>(c, sa_wo, sa_bo, xc, y, MQ, DD, DD, 2);   // y = xc + xs

    // ---- LN2 + MLP + residual ----
    layernorm_k<<<MQ, 128>>>(y, ln2_g, ln2_b, xn);
    gemm_mma<<<gh, blk>>>(xn, mlp_w1, mlp_b1, nullptr, h1, MQ, HID, DD, 1);  // GELU
    gemm_mma<<<gq, blk>>>(h1, mlp_w2, mlp_b2, y, out, MQ, DD, HID, 2);       // + y
}

// round 12
// speedup vs baseline: 6.7872x; 1.0431x over previous
#include <cuda_runtime.h>
#include <cuda_fp16.h>
#include <math.h>
#include <stdint.h>

// ---------------------------------------------------------------------------
// Problem constants
// ---------------------------------------------------------------------------
#define BB   2
#define NQ   2048
#define NK   4096
#define DD   512
#define HH   8
#define HID  2048
#define MQ   (BB*NQ)   // 4096
#define MK   (BB*NK)   // 8192

// ---------------------------------------------------------------------------
// Scratch (static device globals; no runtime allocation)
// ---------------------------------------------------------------------------
__device__ __align__(16) float  g_xc[MQ*DD];
__device__ __align__(16) float  g_y [MQ*DD];
__device__ __align__(16) __half g_xh [MQ*DD];
__device__ __align__(16) __half g_crh[MK*DD];
__device__ __align__(16) __half g_qh [MQ*DD];
__device__ __align__(16) __half g_kh [MK*DD];
__device__ __align__(16) __half g_vh [MK*DD];
__device__ __align__(16) __half g_ch [MQ*DD];
__device__ __align__(16) __half g_xnh[MQ*DD];
__device__ __align__(16) __half g_h1h[MQ*HID];
// fp16 weights: 8 x [512,512] + [512,2048] + [2048,512]
__device__ __align__(16) __half g_wh[8*DD*DD + 2*DD*HID];

// ---------------------------------------------------------------------------
// PTX helpers (all family-portable: valid on plain sm_103 target)
// ---------------------------------------------------------------------------
__device__ __forceinline__ uint32_t cvta_smem(const void* p) {
    uint32_t a;
    asm("{ .reg .u64 t; cvta.to.shared.u64 t, %1; cvt.u32.u64 %0, t; }"
        : "=r"(a) : "l"(p));
    return a;
}

__device__ __forceinline__ void ldsm4(uint32_t r[4], uint32_t a) {
    asm volatile("ldmatrix.sync.aligned.m8n8.x4.shared.b16 {%0,%1,%2,%3}, [%4];"
        : "=r"(r[0]), "=r"(r[1]), "=r"(r[2]), "=r"(r[3]) : "r"(a));
}
__device__ __forceinline__ void ldsm4t(uint32_t r[4], uint32_t a) {
    asm volatile("ldmatrix.sync.aligned.m8n8.x4.trans.shared.b16 {%0,%1,%2,%3}, [%4];"
        : "=r"(r[0]), "=r"(r[1]), "=r"(r[2]), "=r"(r[3]) : "r"(a));
}

__device__ __forceinline__ void mma_f16(float c[4],
                                        uint32_t a0, uint32_t a1,
                                        uint32_t a2, uint32_t a3,
                                        uint32_t b0, uint32_t b1)
{
    asm volatile(
        "mma.sync.aligned.m16n8k16.row.col.f32.f16.f16.f32 "
        "{%0,%1,%2,%3}, {%4,%5,%6,%7}, {%8,%9}, {%0,%1,%2,%3};"
        : "+f"(c[0]), "+f"(c[1]), "+f"(c[2]), "+f"(c[3])
        : "r"(a0), "r"(a1), "r"(a2), "r"(a3), "r"(b0), "r"(b1));
}

__device__ __forceinline__ uint32_t packh2(float lo, float hi) {
    __half2 h = __floats2half2_rn(lo, hi);
    uint32_t u;
    *(__half2*)&u = h;
    return u;
}

#define CPA16(dst, src) \
    asm volatile("cp.async.cg.shared.global [%0], [%1], 16;" \
                 :: "r"(dst), "l"(src) : "memory")
#define CPC() asm volatile("cp.async.commit_group;" ::: "memory")
#define CPW1() asm volatile("cp.async.wait_group 1;" ::: "memory")
#define CPW0() asm volatile("cp.async.wait_group 0;" ::: "memory")

// ---------------------------------------------------------------------------
// fp16 GEMM, cp.async double-buffered: C[M,N] = A[M,K] @ W[K,N] + bias
//   epi bits: 1 = GELU(erf)   2 = add Res (f32)   4 = output fp16
// CTA 128x128, BK=64. 256 threads = 8 warps (4m x 2n), warp 32x64.
// dyn smem: As[2][128*72] + Ws[2][64*136] halves = 71680 B.
// ---------------------------------------------------------------------------
#define GA_STR 72
#define GW_STR 136
#define GEMM_SMEM (2*128*GA_STR*2 + 2*64*GW_STR*2)

__global__ void __launch_bounds__(256)
gemm_mma(const __half* __restrict__ A, const __half* __restrict__ W,
         const float* __restrict__ bias, const float* __restrict__ Res,
         void* __restrict__ Cout, int M, int N, int K, int epi)
{
    extern __shared__ uint16_t smem[];
    uint16_t* As = smem;                        // [2][128*GA_STR]
    uint16_t* Ws = smem + 2 * 128 * GA_STR;     // [2][64*GW_STR]
    const uint32_t as_b = cvta_smem(As);
    const uint32_t ws_b = cvta_smem(Ws);

    const int tid = threadIdx.x;
    const int wid = tid >> 5, lane = tid & 31;
    const int g = lane >> 2, t = lane & 3;
    const int wm = wid >> 1, wn = wid & 1;
    const int m0 = blockIdx.y * 128, n0 = blockIdx.x * 128;
    const int l8 = lane & 7;
    const int s3 = (lane >> 3) & 1;
    const int s4 = (lane >> 4) & 1;

    // loader: A 128 rows x 8 x16B chunks, W 64 rows x 16 chunks (4 iters each)
    const int ar = tid >> 1, ac = (tid & 1) << 2;        // A: 2 thr/row, 4 chunks each
    const int wr = tid >> 2, wc = (tid & 3) << 2;        // W: 4 thr/row, 4 chunks each

    auto load_tile = [&](int buf, int kc) {
        const uint32_t ad = as_b + (uint32_t)(buf * 128 * GA_STR + ar * GA_STR) * 2;
        const __half* ag = A + (size_t)(m0 + ar) * K + kc;
        #pragma unroll
        for (int i = 0; i < 4; ++i)
            CPA16(ad + (uint32_t)(ac + i) * 16, ag + (ac + i) * 8);
        const uint32_t wd = ws_b + (uint32_t)(buf * 64 * GW_STR + wr * GW_STR) * 2;
        const __half* wg = W + (size_t)(kc + wr) * N + n0;
        #pragma unroll
        for (int i = 0; i < 4; ++i)
            CPA16(wd + (uint32_t)(wc + i) * 16, wg + (wc + i) * 8);
    };

    float acc[2][8][4];
    #pragma unroll
    for (int mt = 0; mt < 2; ++mt)
        #pragma unroll
        for (int nt = 0; nt < 8; ++nt)
            #pragma unroll
            for (int j = 0; j < 4; ++j) acc[mt][nt][j] = 0.f;

    const int nchunk = K >> 6;
    load_tile(0, 0);
    CPC();

    for (int ck = 0; ck < nchunk; ++ck) {
        if (ck + 1 < nchunk) { load_tile((ck + 1) & 1, (ck + 1) * 64); CPC(); CPW1(); }
        else                 { CPW0(); }
        __syncthreads();

        const uint32_t ab = as_b + (uint32_t)((ck & 1) * 128 * GA_STR) * 2;
        const uint32_t wb = ws_b + (uint32_t)((ck & 1) * 64 * GW_STR) * 2;

        #pragma unroll
        for (int kk = 0; kk < 4; ++kk) {
            const int k0 = kk * 16;
            uint32_t a[2][4];
            #pragma unroll
            for (int mt = 0; mt < 2; ++mt) {
                const int row = wm * 32 + mt * 16 + l8 + s3 * 8;
                ldsm4(a[mt], ab + (uint32_t)(row * GA_STR + k0 + s4 * 8) * 2);
            }
            #pragma unroll
            for (int ntp = 0; ntp < 4; ++ntp) {
                const int row = k0 + l8 + s3 * 8;
                const int col = wn * 64 + ntp * 16 + s4 * 8;
                uint32_t b[4];
                ldsm4t(b, wb + (uint32_t)(row * GW_STR + col) * 2);
                mma_f16(acc[0][2*ntp  ], a[0][0], a[0][1], a[0][2], a[0][3], b[0], b[1]);
                mma_f16(acc[1][2*ntp  ], a[1][0], a[1][1], a[1][2], a[1][3], b[0], b[1]);
                mma_f16(acc[0][2*ntp+1], a[0][0], a[0][1], a[0][2], a[0][3], b[2], b[3]);
                mma_f16(acc[1][2*ntp+1], a[1][0], a[1][1], a[1][2], a[1][3], b[2], b[3]);
            }
        }
        __syncthreads();
    }

    // Epilogue
    #pragma unroll
    for (int mt = 0; mt < 2; ++mt) {
        #pragma unroll
        for (int nt = 0; nt < 8; ++nt) {
            const int row = m0 + wm * 32 + mt * 16 + g;
            const int col = n0 + wn * 64 + nt * 8 + 2 * t;
            const float bs0 = __ldg(&bias[col]);
            const float bs1 = __ldg(&bias[col + 1]);
            float r0 = acc[mt][nt][0] + bs0;
            float r1 = acc[mt][nt][1] + bs1;
            float r2 = acc[mt][nt][2] + bs0;
            float r3 = acc[mt][nt][3] + bs1;
            if (epi & 1) {
                r0 = 0.5f * r0 * (1.f + erff(r0 * 0.70710678118654752f));
                r1 = 0.5f * r1 * (1.f + erff(r1 * 0.70710678118654752f));
                r2 = 0.5f * r2 * (1.f + erff(r2 * 0.70710678118654752f));
                r3 = 0.5f * r3 * (1.f + erff(r3 * 0.70710678118654752f));
            }
            if (epi & 2) {
                float2 u = *(const float2*)&Res[(size_t)row * N + col];
                float2 w = *(const float2*)&Res[(size_t)(row + 8) * N + col];
                r0 += u.x; r1 += u.y; r2 += w.x; r3 += w.y;
            }
            if (epi & 4) {
                __half* Ch = (__half*)Cout;
                *(uint32_t*)&Ch[(size_t)row * N + col]       = packh2(r0, r1);
                *(uint32_t*)&Ch[(size_t)(row + 8) * N + col] = packh2(r2, r3);
            } else {
                float* Cf = (float*)Cout;
                float2 o0 = {r0, r1}, o1 = {r2, r3};
                *(float2*)&Cf[(size_t)row * N + col] = o0;
                *(float2*)&Cf[(size_t)(row + 8) * N + col] = o1;
            }
        }
    }
}

// ---------------------------------------------------------------------------
// Flash attention, fp16 in/out, cp.async double-buffered K/V.
// CTA = 128 queries x 64 keys, 128 threads (4 warps), warp 32 rows x 64.
// Q unscaled fp16; S accumulator scaled by 0.125 (power of two: bit-exact
// equivalent to pre-scaling Q). P packs straight into fp16 A-fragments.
// dyn smem: Qs[128*72] + Ks[2][64*72] + Vs[2][64*72] halves = 55296 B.
// ---------------------------------------------------------------------------
#define ATT_SMEM ((128*72 + 4*64*72) * 2)

__global__ void __launch_bounds__(128)
attn_mma(const __half* __restrict__ Qg, const __half* __restrict__ Kg,
         const __half* __restrict__ Vg, __half* __restrict__ Og,
         int Nq, int Nk)
{
    extern __shared__ uint16_t sm16[];
    uint16_t* Qs = sm16;                 // [128][72]
    uint16_t* Ks = sm16 + 128 * 72;      // [2][64][72]
    uint16_t* Vs = Ks + 2 * 64 * 72;     // [2][64][72]
    const uint32_t qs_b = cvta_smem(Qs);
    const uint32_t ks_b = cvta_smem(Ks);
    const uint32_t vs_b = cvta_smem(Vs);

    const int tid = threadIdx.x;
    const int wid = tid >> 5, lane = tid & 31;
    const int g = lane >> 2, t = lane & 3;
    const int l8 = lane & 7;
    const int s3 = (lane >> 3) & 1;
    const int s4 = (lane >> 4) & 1;
    const int b = blockIdx.z, h = blockIdx.y;
    const int q0 = blockIdx.x * 128;

    const __half* qbase = Qg + (size_t)(b * Nq + q0) * DD + h * 64;
    const __half* kbase = Kg + (size_t)b * Nk * DD + h * 64;
    const __half* vbase = Vg + (size_t)b * Nk * DD + h * 64;

    // loader indices: tile rows 64/128, 8 x16B chunks per row
    const int qr = tid >> 1, qc = (tid & 1) << 2;   // Q: 2 thr/row, 4 chunks
    const int kr = tid >> 3, kc8 = (tid & 7);       // K/V: 8 thr/row, 1 chunk; x8 rows per iter? no:
    // K/V tile: 64 rows x 8 chunks = 512 chunks; 128 threads -> 4 chunks each.
    // Use: row = tid>>1 (0..63), chunk pair base = (tid&1)*4, 4 consecutive.
    const int vr = tid >> 1, vc = (tid & 1) << 2;

    auto load_q = [&]() {
        const uint32_t qd = qs_b + (uint32_t)(qr * 72) * 2;
        const __half* qg = qbase + (size_t)qr * DD;
        #pragma unroll
        for (int i = 0; i < 4; ++i)
            CPA16(qd + (uint32_t)(qc + i) * 16, qg + (qc + i) * 8);
        // second half of Q rows (64..127)
        const uint32_t qd2 = qs_b + (uint32_t)((qr + 64) * 72) * 2;
        const __half* qg2 = qbase + (size_t)(qr + 64) * DD;
        #pragma unroll
        for (int i = 0; i < 4; ++i)
            CPA16(qd2 + (uint32_t)(qc + i) * 16, qg2 + (qc + i) * 8);
    };
    auto load_kv = [&](int buf, int kb) {
        const uint32_t kd = ks_b + (uint32_t)(buf * 64 * 72 + vr * 72) * 2;
        const __half* kg = kbase + (size_t)(kb * 64 + vr) * DD;
        #pragma unroll
        for (int i = 0; i < 4; ++i)
            CPA16(kd + (uint32_t)(vc + i) * 16, kg + (vc + i) * 8);
        const uint32_t vd = vs_b + (uint32_t)(buf * 64 * 72 + vr * 72) * 2;
        const __half* vg = vbase + (size_t)(kb * 64 + vr) * DD;
        #pragma unroll
        for (int i = 0; i < 4; ++i)
            CPA16(vd + (uint32_t)(vc + i) * 16, vg + (vc + i) * 8);
    };

    float m_i[4], l_i[4];
    float o[2][8][4];
    #pragma unroll
    for (int i = 0; i < 4; ++i) { m_i[i] = -1e30f; l_i[i] = 0.f; }
    #pragma unroll
    for (int mt = 0; mt < 2; ++mt)
        #pragma unroll
        for (int nt = 0; nt < 8; ++nt)
            #pragma unroll
            for (int j = 0; j < 4; ++j) o[mt][nt][j] = 0.f;

    const int rw = wid * 32;
    const int nT = Nk >> 6;

    load_q();
    load_kv(0, 0);
    CPC();

    for (int kb = 0; kb < nT; ++kb) {
        if (kb + 1 < nT) { load_kv((kb + 1) & 1, kb + 1); CPC(); CPW1(); }
        else             { CPW0(); }
        __syncthreads();

        const uint32_t kbuf = ks_b + (uint32_t)((kb & 1) * 64 * 72) * 2;
        const uint32_t vbuf = vs_b + (uint32_t)((kb & 1) * 64 * 72) * 2;

        // S = Q @ K^T
        float s[2][8][4];
        #pragma unroll
        for (int mt = 0; mt < 2; ++mt)
            #pragma unroll
            for (int nt = 0; nt < 8; ++nt)
                #pragma unroll
                for (int j = 0; j < 4; ++j) s[mt][nt][j] = 0.f;

        #pragma unroll
        for (int kk = 0; kk < 4; ++kk) {
            const int k0 = kk * 16;
            uint32_t a[2][4];
            #pragma unroll
            for (int mt = 0; mt < 2; ++mt) {
                const int row = rw + mt * 16 + l8 + s3 * 8;
                ldsm4(a[mt], qs_b + (uint32_t)(row * 72 + k0 + s4 * 8) * 2);
            }
            #pragma unroll
            for (int ntp = 0; ntp < 4; ++ntp) {
                const int row = ntp * 16 + l8 + s4 * 8;
                uint32_t bf[4];
                ldsm4(bf, kbuf + (uint32_t)(row * 72 + k0 + s3 * 8) * 2);
                mma_f16(s[0][2*ntp  ], a[0][0], a[0][1], a[0][2], a[0][3], bf[0], bf[1]);
                mma_f16(s[1][2*ntp  ], a[1][0], a[1][1], a[1][2], a[1][3], bf[0], bf[1]);
                mma_f16(s[0][2*ntp+1], a[0][0], a[0][1], a[0][2], a[0][3], bf[2], bf[3]);
                mma_f16(s[1][2*ntp+1], a[1][0], a[1][1], a[1][2], a[1][3], bf[2], bf[3]);
            }
        }

        // scale by d^-0.5 (exact power of two)
        #pragma unroll
        for (int mt = 0; mt < 2; ++mt)
            #pragma unroll
            for (int nt = 0; nt < 8; ++nt)
                #pragma unroll
                for (int j = 0; j < 4; ++j) s[mt][nt][j] *= 0.125f;

        // Online softmax + pack P into fp16 A-fragments
        uint32_t pa[2][4][4];
        #pragma unroll
        for (int mt = 0; mt < 2; ++mt) {
            float rmax0 = -1e30f, rmax1 = -1e30f;
            #pragma unroll
            for (int nt = 0; nt < 8; ++nt) {
                rmax0 = fmaxf(rmax0, fmaxf(s[mt][nt][0], s[mt][nt][1]));
                rmax1 = fmaxf(rmax1, fmaxf(s[mt][nt][2], s[mt][nt][3]));
            }
            rmax0 = fmaxf(rmax0, __shfl_xor_sync(0xffffffffu, rmax0, 1));
            rmax0 = fmaxf(rmax0, __shfl_xor_sync(0xffffffffu, rmax0, 2));
            rmax1 = fmaxf(rmax1, __shfl_xor_sync(0xffffffffu, rmax1, 1));
            rmax1 = fmaxf(rmax1, __shfl_xor_sync(0xffffffffu, rmax1, 2));

            const float mn0 = fmaxf(m_i[mt * 2 + 0], rmax0);
            const float mn1 = fmaxf(m_i[mt * 2 + 1], rmax1);
            const float corr0 = __expf(m_i[mt * 2 + 0] - mn0);
            const float corr1 = __expf(m_i[mt * 2 + 1] - mn1);

            float rs0 = 0.f, rs1 = 0.f;
            #pragma unroll
            for (int nt = 0; nt < 8; ++nt) {
                float p0 = __expf(s[mt][nt][0] - mn0);
                float p1 = __expf(s[mt][nt][1] - mn0);
                float p2 = __expf(s[mt][nt][2] - mn1);
                float p3 = __expf(s[mt][nt][3] - mn1);
                rs0 += p0 + p1;
                rs1 += p2 + p3;
                const int kp = nt >> 1, half = (nt & 1) * 2;
                pa[mt][kp][half + 0] = packh2(p0, p1);
                pa[mt][kp][half + 1] = packh2(p2, p3);
            }
            rs0 += __shfl_xor_sync(0xffffffffu, rs0, 1);
            rs0 += __shfl_xor_sync(0xffffffffu, rs0, 2);
            rs1 += __shfl_xor_sync(0xffffffffu, rs1, 1);
            rs1 += __shfl_xor_sync(0xffffffffu, rs1, 2);

            l_i[mt * 2 + 0] = l_i[mt * 2 + 0] * corr0 + rs0;
            l_i[mt * 2 + 1] = l_i[mt * 2 + 1] * corr1 + rs1;
            m_i[mt * 2 + 0] = mn0;
            m_i[mt * 2 + 1] = mn1;
            #pragma unroll
            for (int nt = 0; nt < 8; ++nt) {
                o[mt][nt][0] *= corr0; o[mt][nt][1] *= corr0;
                o[mt][nt][2] *= corr1; o[mt][nt][3] *= corr1;
            }
        }

        // O += P @ V
        #pragma unroll
        for (int kp = 0; kp < 4; ++kp) {
            const int k0 = kp * 16;
            #pragma unroll
            for (int ntp = 0; ntp < 4; ++ntp) {
                const int row = k0 + l8 + s3 * 8;
                const int col = ntp * 16 + s4 * 8;
                uint32_t bf[4];
                ldsm4t(bf, vbuf + (uint32_t)(row * 72 + col) * 2);
                mma_f16(o[0][2*ntp  ], pa[0][kp][0], pa[0][kp][1], pa[0][kp][2], pa[0][kp][3], bf[0], bf[1]);
                mma_f16(o[1][2*ntp  ], pa[1][kp][0], pa[1][kp][1], pa[1][kp][2], pa[1][kp][3], bf[0], bf[1]);
                mma_f16(o[0][2*ntp+1], pa[0][kp][0], pa[0][kp][1], pa[0][kp][2], pa[0][kp][3], bf[2], bf[3]);
                mma_f16(o[1][2*ntp+1], pa[1][kp][0], pa[1][kp][1], pa[1][kp][2], pa[1][kp][3], bf[2], bf[3]);
            }
        }
        __syncthreads();   // all warps done with this K/V buffer before reload
    }

    // Normalize + write fp16
    #pragma unroll
    for (int mt = 0; mt < 2; ++mt) {
        const float inv0 = 1.0f / l_i[mt * 2 + 0];
        const float inv1 = 1.0f / l_i[mt * 2 + 1];
        const int r0g = b * Nq + q0 + rw + mt * 16 + g;
        #pragma unroll
        for (int nt = 0; nt < 8; ++nt) {
            const int col = h * 64 + nt * 8 + 2 * t;
            *(uint32_t*)&Og[(size_t)r0g * DD + col] =
                packh2(o[mt][nt][0] * inv0, o[mt][nt][1] * inv0);
            *(uint32_t*)&Og[(size_t)(r0g + 8) * DD + col] =
                packh2(o[mt][nt][2] * inv1, o[mt][nt][3] * inv1);
        }
    }
}

// ---------------------------------------------------------------------------
// LayerNorm over last dim (512), biased variance, eps=1e-5. fp32 in, fp16 out.
// ---------------------------------------------------------------------------
__global__ void __launch_bounds__(128)
layernorm_k(const float* __restrict__ X, const float* __restrict__ gam,
            const float* __restrict__ bet, __half* __restrict__ Y)
{
    __shared__ float red[8];
    const int row = blockIdx.x, tid = threadIdx.x;
    float4 v = *(const float4*)&X[(size_t)row * DD + tid * 4];
    float s  = v.x + v.y + v.z + v.w;
    float ss = v.x * v.x + v.y * v.y + v.z * v.z + v.w * v.w;
    #pragma unroll
    for (int o = 16; o; o >>= 1) {
        s  += __shfl_xor_sync(0xffffffffu, s, o);
        ss += __shfl_xor_sync(0xffffffffu, ss, o);
    }
    if ((tid & 31) == 0) { red[tid >> 5] = s; red[4 + (tid >> 5)] = ss; }
    __syncthreads();
    s  = red[0] + red[1] + red[2] + red[3];
    ss = red[4] + red[5] + red[6] + red[7];
    float mean = s * (1.f / 512.f);
    float var  = ss * (1.f / 512.f) - mean * mean;
    float rstd = rsqrtf(var + 1e-5f);
    float4 g4 = *(const float4*)&gam[tid * 4];
    float4 b4 = *(const float4*)&bet[tid * 4];
    float o0 = (v.x - mean) * rstd * g4.x + b4.x;
    float o1 = (v.y - mean) * rstd * g4.y + b4.y;
    float o2 = (v.z - mean) * rstd * g4.z + b4.z;
    float o3 = (v.w - mean) * rstd * g4.w + b4.w;
    uint2 u = { packh2(o0, o1), packh2(o2, o3) };
    *(uint2*)&Y[(size_t)row * DD + tid * 4] = u;
}

// ---------------------------------------------------------------------------
// f32 -> f16 elementwise convert (n multiple of 4)
// ---------------------------------------------------------------------------
__global__ void __launch_bounds__(256)
cvt16_k(const float* __restrict__ src, __half* __restrict__ dst, int n)
{
    int i = (blockIdx.x * 256 + threadIdx.x) * 4;
    if (i < n) {
        float4 v = *(const float4*)(src + i);
        uint2 u = { packh2(v.x, v.y), packh2(v.z, v.w) };
        *(uint2*)(dst + i) = u;
    }
}

// ---------------------------------------------------------------------------
// Host orchestration (graph-capturable: kernel launches only)
// ---------------------------------------------------------------------------
extern "C" void kernel_launch(void* const* d_in, const int* in_sizes, int n_in,
                              void* d_out, int out_size)
{
    const float* x      = (const float*)d_in[0];
    const float* cross  = (const float*)d_in[1];
    const float* ca_wq  = (const float*)d_in[2];
    const float* ca_bq  = (const float*)d_in[3];
    const float* ca_wk  = (const float*)d_in[4];
    const float* ca_bk  = (const float*)d_in[5];
    const float* ca_wv  = (const float*)d_in[6];
    const float* ca_bv  = (const float*)d_in[7];
    const float* ca_wo  = (const float*)d_in[8];
    const float* ca_bo  = (const float*)d_in[9];
    const float* sa_wq  = (const float*)d_in[10];
    const float* sa_bq  = (const float*)d_in[11];
    const float* sa_wk  = (const float*)d_in[12];
    const float* sa_bk  = (const float*)d_in[13];
    const float* sa_wv  = (const float*)d_in[14];
    const float* sa_bv  = (const float*)d_in[15];
    const float* sa_wo  = (const float*)d_in[16];
    const float* sa_bo  = (const float*)d_in[17];
    const float* ln1_g  = (const float*)d_in[18];
    const float* ln1_b  = (const float*)d_in[19];
    const float* ln2_g  = (const float*)d_in[20];
    const float* ln2_b  = (const float*)d_in[21];
    const float* mlp_w1 = (const float*)d_in[22];
    const float* mlp_b1 = (const float*)d_in[23];
    const float* mlp_w2 = (const float*)d_in[24];
    const float* mlp_b2 = (const float*)d_in[25];
    float* out = (float*)d_out;

    float *xc, *y;
    __half *xh, *crh, *qh, *kh, *vh, *ch, *xnh, *h1h, *wh;
    cudaGetSymbolAddress((void**)&xc,  g_xc);
    cudaGetSymbolAddress((void**)&y,   g_y);
    cudaGetSymbolAddress((void**)&xh,  g_xh);
    cudaGetSymbolAddress((void**)&crh, g_crh);
    cudaGetSymbolAddress((void**)&qh,  g_qh);
    cudaGetSymbolAddress((void**)&kh,  g_kh);
    cudaGetSymbolAddress((void**)&vh,  g_vh);
    cudaGetSymbolAddress((void**)&ch,  g_ch);
    cudaGetSymbolAddress((void**)&xnh, g_xnh);
    cudaGetSymbolAddress((void**)&h1h, g_h1h);
    cudaGetSymbolAddress((void**)&wh,  g_wh);

    __half* w_caq = wh + 0 * DD * DD;
    __half* w_cak = wh + 1 * DD * DD;
    __half* w_cav = wh + 2 * DD * DD;
    __half* w_cao = wh + 3 * DD * DD;
    __half* w_saq = wh + 4 * DD * DD;
    __half* w_sak = wh + 5 * DD * DD;
    __half* w_sav = wh + 6 * DD * DD;
    __half* w_sao = wh + 7 * DD * DD;
    __half* w_m1  = wh + 8 * DD * DD;              // [512, 2048]
    __half* w_m2  = wh + 8 * DD * DD + DD * HID;   // [2048, 512]

    cudaFuncSetAttribute(gemm_mma, cudaFuncAttributeMaxDynamicSharedMemorySize,
                         GEMM_SMEM);
    cudaFuncSetAttribute(attn_mma, cudaFuncAttributeMaxDynamicSharedMemorySize,
                         ATT_SMEM);

    // ---- fp16 conversions (once per launch; ~16MB total reads) ----
    const int CT = 256;
    cvt16_k<<<(MQ*DD/4 + CT-1)/CT, CT>>>(x,      xh,   MQ*DD);
    cvt16_k<<<(MK*DD/4 + CT-1)/CT, CT>>>(cross,  crh,  MK*DD);
    cvt16_k<<<(DD*DD/4 + CT-1)/CT, CT>>>(ca_wq,  w_caq, DD*DD);
    cvt16_k<<<(DD*DD/4 + CT-1)/CT, CT>>>(ca_wk,  w_cak, DD*DD);
    cvt16_k<<<(DD*DD/4 + CT-1)/CT, CT>>>(ca_wv,  w_cav, DD*DD);
    cvt16_k<<<(DD*DD/4 + CT-1)/CT, CT>>>(ca_wo,  w_cao, DD*DD);
    cvt16_k<<<(DD*DD/4 + CT-1)/CT, CT>>>(sa_wq,  w_saq, DD*DD);
    cvt16_k<<<(DD*DD/4 + CT-1)/CT, CT>>>(sa_wk,  w_sak, DD*DD);
    cvt16_k<<<(DD*DD/4 + CT-1)/CT, CT>>>(sa_wv,  w_sav, DD*DD);
    cvt16_k<<<(DD*DD/4 + CT-1)/CT, CT>>>(sa_wo,  w_sao, DD*DD);
    cvt16_k<<<(DD*HID/4 + CT-1)/CT, CT>>>(mlp_w1, w_m1, DD*HID);
    cvt16_k<<<(DD*HID/4 + CT-1)/CT, CT>>>(mlp_w2, w_m2, DD*HID);

    const dim3 blk(256);
    const dim3 gq(DD / 128, MQ / 128);    // 4 x 32
    const dim3 gk(DD / 128, MK / 128);    // 4 x 64
    const dim3 gh(HID / 128, MQ / 128);   // 16 x 32
    const dim3 ga(NQ / 128, HH, BB);      // 16 x 8 x 2

    // ---- cross-attention ----
    gemm_mma<<<gq, blk, GEMM_SMEM>>>(xh,  w_caq, ca_bq, nullptr, qh, MQ, DD, DD, 4);
    gemm_mma<<<gk, blk, GEMM_SMEM>>>(crh, w_cak, ca_bk, nullptr, kh, MK, DD, DD, 4);
    gemm_mma<<<gk, blk, GEMM_SMEM>>>(crh, w_cav, ca_bv, nullptr, vh, MK, DD, DD, 4);
    attn_mma<<<ga, 128, ATT_SMEM>>>(qh, kh, vh, ch, NQ, NK);
    gemm_mma<<<gq, blk, GEMM_SMEM>>>(ch, w_cao, ca_bo, nullptr, xc, MQ, DD, DD, 0);

    // ---- LN1 + self-attention ----
    layernorm_k<<<MQ, 128>>>(xc, ln1_g, ln1_b, xnh);
    gemm_mma<<<gq, blk, GEMM_SMEM>>>(xnh, w_saq, sa_bq, nullptr, qh, MQ, DD, DD, 4);
    gemm_mma<<<gq, blk, GEMM_SMEM>>>(xnh, w_sak, sa_bk, nullptr, kh, MQ, DD, DD, 4);
    gemm_mma<<<gq, blk, GEMM_SMEM>>>(xnh, w_sav, sa_bv, nullptr, vh, MQ, DD, DD, 4);
    attn_mma<<<ga, 128, ATT_SMEM>>>(qh, kh, vh, ch, NQ, NQ);
    gemm_mma<<<gq, blk, GEMM_SMEM>>>(ch, w_sao, sa_bo, xc, y, MQ, DD, DD, 2);  // y = xc + xs

    // ---- LN2 + MLP + residual ----
    layernorm_k<<<MQ, 128>>>(y, ln2_g, ln2_b, xnh);
    gemm_mma<<<gh, blk, GEMM_SMEM>>>(xnh, w_m1, mlp_b1, nullptr, h1h, MQ, HID, DD, 5);  // GELU->fp16
    gemm_mma<<<gq, blk, GEMM_SMEM>>>(h1h, w_m2, mlp_b2, y, out, MQ, DD, HID, 2);        // + y
}

// round 14
// speedup vs baseline: 7.2716x; 1.0714x over previous
#include <cuda_runtime.h>
#include <cuda_fp16.h>
#include <math.h>
#include <stdint.h>

// ---------------------------------------------------------------------------
// Problem constants
// ---------------------------------------------------------------------------
#define BB   2
#define NQ   2048
#define NK   4096
#define DD   512
#define HH   8
#define HID  2048
#define MQ   (BB*NQ)   // 4096
#define MK   (BB*NK)   // 8192

// ---------------------------------------------------------------------------
// Scratch (static device globals; no runtime allocation)
// ---------------------------------------------------------------------------
__device__ __align__(16) float  g_xc[MQ*DD];
__device__ __align__(16) float  g_y [MQ*DD];
__device__ __align__(16) __half g_xh [MQ*DD];
__device__ __align__(16) __half g_crh[MK*DD];
__device__ __align__(16) __half g_qh [MQ*DD];
__device__ __align__(16) __half g_kh [MK*DD];
__device__ __align__(16) __half g_vh [MK*DD];
__device__ __align__(16) __half g_ch [MQ*DD];
__device__ __align__(16) __half g_xnh[MQ*DD];
__device__ __align__(16) __half g_h1h[MQ*HID];
__device__ __align__(16) __half g_wh[8*DD*DD + 2*DD*HID];

// ---------------------------------------------------------------------------
// PTX helpers (family-portable; valid on plain sm_103 target)
// ---------------------------------------------------------------------------
__device__ __forceinline__ uint32_t cvta_smem(const void* p) {
    uint32_t a;
    asm("{ .reg .u64 t; cvta.to.shared.u64 t, %1; cvt.u32.u64 %0, t; }"
        : "=r"(a) : "l"(p));
    return a;
}

__device__ __forceinline__ void ldsm4(uint32_t r[4], uint32_t a) {
    asm volatile("ldmatrix.sync.aligned.m8n8.x4.shared.b16 {%0,%1,%2,%3}, [%4];"
        : "=r"(r[0]), "=r"(r[1]), "=r"(r[2]), "=r"(r[3]) : "r"(a));
}
__device__ __forceinline__ void ldsm4t(uint32_t r[4], uint32_t a) {
    asm volatile("ldmatrix.sync.aligned.m8n8.x4.trans.shared.b16 {%0,%1,%2,%3}, [%4];"
        : "=r"(r[0]), "=r"(r[1]), "=r"(r[2]), "=r"(r[3]) : "r"(a));
}

__device__ __forceinline__ void mma_f16(float c[4],
                                        uint32_t a0, uint32_t a1,
                                        uint32_t a2, uint32_t a3,
                                        uint32_t b0, uint32_t b1)
{
    asm volatile(
        "mma.sync.aligned.m16n8k16.row.col.f32.f16.f16.f32 "
        "{%0,%1,%2,%3}, {%4,%5,%6,%7}, {%8,%9}, {%0,%1,%2,%3};"
        : "+f"(c[0]), "+f"(c[1]), "+f"(c[2]), "+f"(c[3])
        : "r"(a0), "r"(a1), "r"(a2), "r"(a3), "r"(b0), "r"(b1));
}

__device__ __forceinline__ uint32_t packh2(float lo, float hi) {
    __half2 h = __floats2half2_rn(lo, hi);
    uint32_t u;
    *(__half2*)&u = h;
    return u;
}

#define CPA16(dst, src) \
    asm volatile("cp.async.cg.shared.global [%0], [%1], 16;" \
                 :: "r"(dst), "l"(src) : "memory")
#define CPC() asm volatile("cp.async.commit_group;" ::: "memory")
#define CPW1() asm volatile("cp.async.wait_group 1;" ::: "memory")
#define CPW0() asm volatile("cp.async.wait_group 0;" ::: "memory")

// ---------------------------------------------------------------------------
// Shared GEMM mainloop (cp.async double-buffered, CTA 128x128, BK=64,
// 256 threads = 8 warps (4m x 2n), warp 32x64). Fills acc[2][8][4].
// ---------------------------------------------------------------------------
#define GA_STR 72
#define GW_STR 136
#define GEMM_SMEM (2*128*GA_STR*2 + 2*64*GW_STR*2)

__device__ __forceinline__ void gemm_body(
    const __half* __restrict__ A, const __half* __restrict__ W,
    int N, int K, int m0, int n0,
    uint32_t as_b, uint32_t ws_b, float acc[2][8][4])
{
    const int tid = threadIdx.x;
    const int wid = tid >> 5, lane = tid & 31;
    const int wm = wid >> 1, wn = wid & 1;
    const int l8 = lane & 7;
    const int s3 = (lane >> 3) & 1;
    const int s4 = (lane >> 4) & 1;

    const int ar = tid >> 1, ac = (tid & 1) << 2;
    const int wr = tid >> 2, wc = (tid & 3) << 2;

    auto load_tile = [&](int buf, int kc) {
        const uint32_t ad = as_b + (uint32_t)(buf * 128 * GA_STR + ar * GA_STR) * 2;
        const __half* ag = A + (size_t)(m0 + ar) * K + kc;
        #pragma unroll
        for (int i = 0; i < 4; ++i)
            CPA16(ad + (uint32_t)(ac + i) * 16, ag + (ac + i) * 8);
        const uint32_t wd = ws_b + (uint32_t)(buf * 64 * GW_STR + wr * GW_STR) * 2;
        const __half* wg = W + (size_t)(kc + wr) * N + n0;
        #pragma unroll
        for (int i = 0; i < 4; ++i)
            CPA16(wd + (uint32_t)(wc + i) * 16, wg + (wc + i) * 8);
    };

    const int nchunk = K >> 6;
    load_tile(0, 0);
    CPC();

    for (int ck = 0; ck < nchunk; ++ck) {
        if (ck + 1 < nchunk) { load_tile((ck + 1) & 1, (ck + 1) * 64); CPC(); CPW1(); }
        else                 { CPW0(); }
        __syncthreads();

        const uint32_t ab = as_b + (uint32_t)((ck & 1) * 128 * GA_STR) * 2;
        const uint32_t wb = ws_b + (uint32_t)((ck & 1) * 64 * GW_STR) * 2;

        #pragma unroll
        for (int kk = 0; kk < 4; ++kk) {
            const int k0 = kk * 16;
            uint32_t a[2][4];
            #pragma unroll
            for (int mt = 0; mt < 2; ++mt) {
                const int row = wm * 32 + mt * 16 + l8 + s3 * 8;
                ldsm4(a[mt], ab + (uint32_t)(row * GA_STR + k0 + s4 * 8) * 2);
            }
            #pragma unroll
            for (int ntp = 0; ntp < 4; ++ntp) {
                const int row = k0 + l8 + s3 * 8;
                const int col = wn * 64 + ntp * 16 + s4 * 8;
                uint32_t b[4];
                ldsm4t(b, wb + (uint32_t)(row * GW_STR + col) * 2);
                mma_f16(acc[0][2*ntp  ], a[0][0], a[0][1], a[0][2], a[0][3], b[0], b[1]);
                mma_f16(acc[1][2*ntp  ], a[1][0], a[1][1], a[1][2], a[1][3], b[0], b[1]);
                mma_f16(acc[0][2*ntp+1], a[0][0], a[0][1], a[0][2], a[0][3], b[2], b[3]);
                mma_f16(acc[1][2*ntp+1], a[1][0], a[1][1], a[1][2], a[1][3], b[2], b[3]);
            }
        }
        __syncthreads();
    }
}

// ---------------------------------------------------------------------------
// General GEMM: epi bits: 1 = GELU(erf)  2 = add Res(f32)  4 = fp16 out
// ---------------------------------------------------------------------------
__global__ void __launch_bounds__(256)
gemm_mma(const __half* __restrict__ A, const __half* __restrict__ W,
         const float* __restrict__ bias, const float* __restrict__ Res,
         void* __restrict__ Cout, int M, int N, int K, int epi)
{
    extern __shared__ uint16_t smem[];
    const uint32_t as_b = cvta_smem(smem);
    const uint32_t ws_b = cvta_smem(smem + 2 * 128 * GA_STR);
    const int m0 = blockIdx.y * 128, n0 = blockIdx.x * 128;

    float acc[2][8][4];
    #pragma unroll
    for (int mt = 0; mt < 2; ++mt)
        #pragma unroll
        for (int nt = 0; nt < 8; ++nt)
            #pragma unroll
            for (int j = 0; j < 4; ++j) acc[mt][nt][j] = 0.f;

    gemm_body(A, W, N, K, m0, n0, as_b, ws_b, acc);

    const int tid = threadIdx.x;
    const int wid = tid >> 5, lane = tid & 31;
    const int g = lane >> 2, t = lane & 3;
    const int wm = wid >> 1, wn = wid & 1;

    #pragma unroll
    for (int mt = 0; mt < 2; ++mt) {
        #pragma unroll
        for (int nt = 0; nt < 8; ++nt) {
            const int row = m0 + wm * 32 + mt * 16 + g;
            const int col = n0 + wn * 64 + nt * 8 + 2 * t;
            const float bs0 = __ldg(&bias[col]);
            const float bs1 = __ldg(&bias[col + 1]);
            float r0 = acc[mt][nt][0] + bs0;
            float r1 = acc[mt][nt][1] + bs1;
            float r2 = acc[mt][nt][2] + bs0;
            float r3 = acc[mt][nt][3] + bs1;
            if (epi & 1) {
                r0 = 0.5f * r0 * (1.f + erff(r0 * 0.70710678118654752f));
                r1 = 0.5f * r1 * (1.f + erff(r1 * 0.70710678118654752f));
                r2 = 0.5f * r2 * (1.f + erff(r2 * 0.70710678118654752f));
                r3 = 0.5f * r3 * (1.f + erff(r3 * 0.70710678118654752f));
            }
            if (epi & 2) {
                float2 u = *(const float2*)&Res[(size_t)row * N + col];
                float2 w = *(const float2*)&Res[(size_t)(row + 8) * N + col];
                r0 += u.x; r1 += u.y; r2 += w.x; r3 += w.y;
            }
            if (epi & 4) {
                __half* Ch = (__half*)Cout;
                *(uint32_t*)&Ch[(size_t)row * N + col]       = packh2(r0, r1);
                *(uint32_t*)&Ch[(size_t)(row + 8) * N + col] = packh2(r2, r3);
            } else {
                float* Cf = (float*)Cout;
                float2 o0 = {r0, r1}, o1 = {r2, r3};
                *(float2*)&Cf[(size_t)row * N + col] = o0;
                *(float2*)&Cf[(size_t)(row + 8) * N + col] = o1;
            }
        }
    }
}

// ---------------------------------------------------------------------------
// Fused QKV GEMM: blockIdx.z selects (A, W, bias, out, M). fp16 out.
// ---------------------------------------------------------------------------
struct QkvArgs {
    const __half* A[3];
    const __half* W[3];
    const float*  bias[3];
    __half*       out[3];
    int           M[3];
};

__global__ void __launch_bounds__(256)
gemm_qkv(QkvArgs q, int N, int K)
{
    const int z = blockIdx.z;
    const int m0 = blockIdx.y * 128, n0 = blockIdx.x * 128;
    if (m0 >= q.M[z]) return;

    extern __shared__ uint16_t smem[];
    const uint32_t as_b = cvta_smem(smem);
    const uint32_t ws_b = cvta_smem(smem + 2 * 128 * GA_STR);

    float acc[2][8][4];
    #pragma unroll
    for (int mt = 0; mt < 2; ++mt)
        #pragma unroll
        for (int nt = 0; nt < 8; ++nt)
            #pragma unroll
            for (int j = 0; j < 4; ++j) acc[mt][nt][j] = 0.f;

    gemm_body(q.A[z], q.W[z], N, K, m0, n0, as_b, ws_b, acc);

    const int tid = threadIdx.x;
    const int wid = tid >> 5, lane = tid & 31;
    const int g = lane >> 2, t = lane & 3;
    const int wm = wid >> 1, wn = wid & 1;
    const float* bias = q.bias[z];
    __half* Ch = q.out[z];

    #pragma unroll
    for (int mt = 0; mt < 2; ++mt) {
        #pragma unroll
        for (int nt = 0; nt < 8; ++nt) {
            const int row = m0 + wm * 32 + mt * 16 + g;
            const int col = n0 + wn * 64 + nt * 8 + 2 * t;
            const float bs0 = __ldg(&bias[col]);
            const float bs1 = __ldg(&bias[col + 1]);
            *(uint32_t*)&Ch[(size_t)row * N + col] =
                packh2(acc[mt][nt][0] + bs0, acc[mt][nt][1] + bs1);
            *(uint32_t*)&Ch[(size_t)(row + 8) * N + col] =
                packh2(acc[mt][nt][2] + bs0, acc[mt][nt][3] + bs1);
        }
    }
}

// ---------------------------------------------------------------------------
// Flash attention, fp16 in/out, cp.async double-buffered K/V.
// CTA = 128 queries x 64 keys, 256 threads = 8 warps, warp = 16 query rows
// (mt=1) x 64 keys/dims. Doubled warp count vs R11 for latency hiding.
// dyn smem: Qs[128*72] + Ks[2][64*72] + Vs[2][64*72] halves = 55296 B.
// ---------------------------------------------------------------------------
#define ATT_SMEM ((128*72 + 4*64*72) * 2)

__global__ void __launch_bounds__(256)
attn_mma(const __half* __restrict__ Qg, const __half* __restrict__ Kg,
         const __half* __restrict__ Vg, __half* __restrict__ Og,
         int Nq, int Nk)
{
    extern __shared__ uint16_t sm16[];
    uint16_t* Qs = sm16;                 // [128][72]
    uint16_t* Ks = sm16 + 128 * 72;      // [2][64][72]
    uint16_t* Vs = Ks + 2 * 64 * 72;     // [2][64][72]
    const uint32_t qs_b = cvta_smem(Qs);
    const uint32_t ks_b = cvta_smem(Ks);
    const uint32_t vs_b = cvta_smem(Vs);

    const int tid = threadIdx.x;
    const int wid = tid >> 5, lane = tid & 31;
    const int g = lane >> 2, t = lane & 3;
    const int l8 = lane & 7;
    const int s3 = (lane >> 3) & 1;
    const int s4 = (lane >> 4) & 1;
    const int b = blockIdx.z, h = blockIdx.y;
    const int q0 = blockIdx.x * 128;

    const __half* qbase = Qg + (size_t)(b * Nq + q0) * DD + h * 64;
    const __half* kbase = Kg + (size_t)b * Nk * DD + h * 64;
    const __half* vbase = Vg + (size_t)b * Nk * DD + h * 64;

    // loaders (256 threads): Q 128 rows x 8 chunks -> 4/thread;
    // K/V 64 rows x 8 chunks -> 2/thread each.
    const int qr = tid >> 1, qc = (tid & 1) << 2;
    const int kr = tid >> 2, kc2 = (tid & 3) << 1;

    auto load_q = [&]() {
        const uint32_t qd = qs_b + (uint32_t)(qr * 72) * 2;
        const __half* qg = qbase + (size_t)qr * DD;
        #pragma unroll
        for (int i = 0; i < 4; ++i)
            CPA16(qd + (uint32_t)(qc + i) * 16, qg + (qc + i) * 8);
    };
    auto load_kv = [&](int buf, int kb) {
        const uint32_t kd = ks_b + (uint32_t)(buf * 64 * 72 + kr * 72) * 2;
        const __half* kg = kbase + (size_t)(kb * 64 + kr) * DD;
        #pragma unroll
        for (int i = 0; i < 2; ++i)
            CPA16(kd + (uint32_t)(kc2 + i) * 16, kg + (kc2 + i) * 8);
        const uint32_t vd = vs_b + (uint32_t)(buf * 64 * 72 + kr * 72) * 2;
        const __half* vg = vbase + (size_t)(kb * 64 + kr) * DD;
        #pragma unroll
        for (int i = 0; i < 2; ++i)
            CPA16(vd + (uint32_t)(kc2 + i) * 16, vg + (kc2 + i) * 8);
    };

    float m_i[2], l_i[2];
    float o[8][4];
    m_i[0] = m_i[1] = -1e30f;
    l_i[0] = l_i[1] = 0.f;
    #pragma unroll
    for (int nt = 0; nt < 8; ++nt)
        #pragma unroll
        for (int j = 0; j < 4; ++j) o[nt][j] = 0.f;

    const int rw = wid * 16;
    const int nT = Nk >> 6;

    load_q();
    load_kv(0, 0);
    CPC();

    for (int kb = 0; kb < nT; ++kb) {
        if (kb + 1 < nT) { load_kv((kb + 1) & 1, kb + 1); CPC(); CPW1(); }
        else             { CPW0(); }
        __syncthreads();

        const uint32_t kbuf = ks_b + (uint32_t)((kb & 1) * 64 * 72) * 2;
        const uint32_t vbuf = vs_b + (uint32_t)((kb & 1) * 64 * 72) * 2;

        // S = Q @ K^T  (warp: 16 rows x 64 keys)
        float s[8][4];
        #pragma unroll
        for (int nt = 0; nt < 8; ++nt)
            #pragma unroll
            for (int j = 0; j < 4; ++j) s[nt][j] = 0.f;

        #pragma unroll
        for (int kk = 0; kk < 4; ++kk) {
            const int k0 = kk * 16;
            uint32_t a[4];
            const int row = rw + l8 + s3 * 8;
            ldsm4(a, qs_b + (uint32_t)(row * 72 + k0 + s4 * 8) * 2);
            #pragma unroll
            for (int ntp = 0; ntp < 4; ++ntp) {
                const int krow = ntp * 16 + l8 + s4 * 8;
                uint32_t bf[4];
                ldsm4(bf, kbuf + (uint32_t)(krow * 72 + k0 + s3 * 8) * 2);
                mma_f16(s[2*ntp  ], a[0], a[1], a[2], a[3], bf[0], bf[1]);
                mma_f16(s[2*ntp+1], a[0], a[1], a[2], a[3], bf[2], bf[3]);
            }
        }

        // scale by d^-0.5 (exact power of two)
        #pragma unroll
        for (int nt = 0; nt < 8; ++nt)
            #pragma unroll
            for (int j = 0; j < 4; ++j) s[nt][j] *= 0.125f;

        // Online softmax + pack P into fp16 A-fragments
        uint32_t pa[4][4];
        {
            float rmax0 = -1e30f, rmax1 = -1e30f;
            #pragma unroll
            for (int nt = 0; nt < 8; ++nt) {
                rmax0 = fmaxf(rmax0, fmaxf(s[nt][0], s[nt][1]));
                rmax1 = fmaxf(rmax1, fmaxf(s[nt][2], s[nt][3]));
            }
            rmax0 = fmaxf(rmax0, __shfl_xor_sync(0xffffffffu, rmax0, 1));
            rmax0 = fmaxf(rmax0, __shfl_xor_sync(0xffffffffu, rmax0, 2));
            rmax1 = fmaxf(rmax1, __shfl_xor_sync(0xffffffffu, rmax1, 1));
            rmax1 = fmaxf(rmax1, __shfl_xor_sync(0xffffffffu, rmax1, 2));

            const float mn0 = fmaxf(m_i[0], rmax0);
            const float mn1 = fmaxf(m_i[1], rmax1);
            const float corr0 = __expf(m_i[0] - mn0);
            const float corr1 = __expf(m_i[1] - mn1);

            float rs0 = 0.f, rs1 = 0.f;
            #pragma unroll
            for (int nt = 0; nt < 8; ++nt) {
                float p0 = __expf(s[nt][0] - mn0);
                float p1 = __expf(s[nt][1] - mn0);
                float p2 = __expf(s[nt][2] - mn1);
                float p3 = __expf(s[nt][3] - mn1);
                rs0 += p0 + p1;
                rs1 += p2 + p3;
                const int kp = nt >> 1, half = (nt & 1) * 2;
                pa[kp][half + 0] = packh2(p0, p1);
                pa[kp][half + 1] = packh2(p2, p3);
            }
            rs0 += __shfl_xor_sync(0xffffffffu, rs0, 1);
            rs0 += __shfl_xor_sync(0xffffffffu, rs0, 2);
            rs1 += __shfl_xor_sync(0xffffffffu, rs1, 1);
            rs1 += __shfl_xor_sync(0xffffffffu, rs1, 2);

            l_i[0] = l_i[0] * corr0 + rs0;
            l_i[1] = l_i[1] * corr1 + rs1;
            m_i[0] = mn0;
            m_i[1] = mn1;
            #pragma unroll
            for (int nt = 0; nt < 8; ++nt) {
                o[nt][0] *= corr0; o[nt][1] *= corr0;
                o[nt][2] *= corr1; o[nt][3] *= corr1;
            }
        }

        // O += P @ V
        #pragma unroll
        for (int kp = 0; kp < 4; ++kp) {
            const int k0 = kp * 16;
            #pragma unroll
            for (int ntp = 0; ntp < 4; ++ntp) {
                const int row = k0 + l8 + s3 * 8;
                const int col = ntp * 16 + s4 * 8;
                uint32_t bf[4];
                ldsm4t(bf, vbuf + (uint32_t)(row * 72 + col) * 2);
                mma_f16(o[2*ntp  ], pa[kp][0], pa[kp][1], pa[kp][2], pa[kp][3], bf[0], bf[1]);
                mma_f16(o[2*ntp+1], pa[kp][0], pa[kp][1], pa[kp][2], pa[kp][3], bf[2], bf[3]);
            }
        }
        __syncthreads();   // all warps done with this K/V buffer before reload
    }

    // Normalize + write fp16
    {
        const float inv0 = 1.0f / l_i[0];
        const float inv1 = 1.0f / l_i[1];
        const int r0g = b * Nq + q0 + rw + g;
        #pragma unroll
        for (int nt = 0; nt < 8; ++nt) {
            const int col = h * 64 + nt * 8 + 2 * t;
            *(uint32_t*)&Og[(size_t)r0g * DD + col] =
                packh2(o[nt][0] * inv0, o[nt][1] * inv0);
            *(uint32_t*)&Og[(size_t)(r0g + 8) * DD + col] =
                packh2(o[nt][2] * inv1, o[nt][3] * inv1);
        }
    }
}

// ---------------------------------------------------------------------------
// LayerNorm over last dim (512), biased variance, eps=1e-5. fp32 in, fp16 out.
// ---------------------------------------------------------------------------
__global__ void __launch_bounds__(128)
layernorm_k(const float* __restrict__ X, const float* __restrict__ gam,
            const float* __restrict__ bet, __half* __restrict__ Y)
{
    __shared__ float red[8];
    const int row = blockIdx.x, tid = threadIdx.x;
    float4 v = *(const float4*)&X[(size_t)row * DD + tid * 4];
    float s  = v.x + v.y + v.z + v.w;
    float ss = v.x * v.x + v.y * v.y + v.z * v.z + v.w * v.w;
    #pragma unroll
    for (int o = 16; o; o >>= 1) {
        s  += __shfl_xor_sync(0xffffffffu, s, o);
        ss += __shfl_xor_sync(0xffffffffu, ss, o);
    }
    if ((tid & 31) == 0) { red[tid >> 5] = s; red[4 + (tid >> 5)] = ss; }
    __syncthreads();
    s  = red[0] + red[1] + red[2] + red[3];
    ss = red[4] + red[5] + red[6] + red[7];
    float mean = s * (1.f / 512.f);
    float var  = ss * (1.f / 512.f) - mean * mean;
    float rstd = rsqrtf(var + 1e-5f);
    float4 g4 = *(const float4*)&gam[tid * 4];
    float4 b4 = *(const float4*)&bet[tid * 4];
    float o0 = (v.x - mean) * rstd * g4.x + b4.x;
    float o1 = (v.y - mean) * rstd * g4.y + b4.y;
    float o2 = (v.z - mean) * rstd * g4.z + b4.z;
    float o3 = (v.w - mean) * rstd * g4.w + b4.w;
    uint2 u = { packh2(o0, o1), packh2(o2, o3) };
    *(uint2*)&Y[(size_t)row * DD + tid * 4] = u;
}

// ---------------------------------------------------------------------------
// f32 -> f16 converts: single tensor, and batched 8x equal-size (grid.y)
// ---------------------------------------------------------------------------
__global__ void __launch_bounds__(256)
cvt16_k(const float* __restrict__ src, __half* __restrict__ dst, int n)
{
    int i = (blockIdx.x * 256 + threadIdx.x) * 4;
    if (i < n) {
        float4 v = *(const float4*)(src + i);
        uint2 u = { packh2(v.x, v.y), packh2(v.z, v.w) };
        *(uint2*)(dst + i) = u;
    }
}

struct Cvt8Args { const float* src[8]; __half* dst[8]; };

__global__ void __launch_bounds__(256)
cvt16x8_k(Cvt8Args a, int n)
{
    const int z = blockIdx.y;
    int i = (blockIdx.x * 256 + threadIdx.x) * 4;
    if (i < n) {
        float4 v = *(const float4*)(a.src[z] + i);
        uint2 u = { packh2(v.x, v.y), packh2(v.z, v.w) };
        *(uint2*)(a.dst[z] + i) = u;
    }
}

// ---------------------------------------------------------------------------
// Host orchestration (graph-capturable: kernel launches only)
// ---------------------------------------------------------------------------
extern "C" void kernel_launch(void* const* d_in, const int* in_sizes, int n_in,
                              void* d_out, int out_size)
{
    const float* x      = (const float*)d_in[0];
    const float* cross  = (const float*)d_in[1];
    const float* ca_wq  = (const float*)d_in[2];
    const float* ca_bq  = (const float*)d_in[3];
    const float* ca_wk  = (const float*)d_in[4];
    const float* ca_bk  = (const float*)d_in[5];
    const float* ca_wv  = (const float*)d_in[6];
    const float* ca_bv  = (const float*)d_in[7];
    const float* ca_wo  = (const float*)d_in[8];
    const float* ca_bo  = (const float*)d_in[9];
    const float* sa_wq  = (const float*)d_in[10];
    const float* sa_bq  = (const float*)d_in[11];
    const float* sa_wk  = (const float*)d_in[12];
    const float* sa_bk  = (const float*)d_in[13];
    const float* sa_wv  = (const float*)d_in[14];
    const float* sa_bv  = (const float*)d_in[15];
    const float* sa_wo  = (const float*)d_in[16];
    const float* sa_bo  = (const float*)d_in[17];
    const float* ln1_g  = (const float*)d_in[18];
    const float* ln1_b  = (const float*)d_in[19];
    const float* ln2_g  = (const float*)d_in[20];
    const float* ln2_b  = (const float*)d_in[21];
    const float* mlp_w1 = (const float*)d_in[22];
    const float* mlp_b1 = (const float*)d_in[23];
    const float* mlp_w2 = (const float*)d_in[24];
    const float* mlp_b2 = (const float*)d_in[25];
    float* out = (float*)d_out;

    float *xc, *y;
    __half *xh, *crh, *qh, *kh, *vh, *ch, *xnh, *h1h, *wh;
    cudaGetSymbolAddress((void**)&xc,  g_xc);
    cudaGetSymbolAddress((void**)&y,   g_y);
    cudaGetSymbolAddress((void**)&xh,  g_xh);
    cudaGetSymbolAddress((void**)&crh, g_crh);
    cudaGetSymbolAddress((void**)&qh,  g_qh);
    cudaGetSymbolAddress((void**)&kh,  g_kh);
    cudaGetSymbolAddress((void**)&vh,  g_vh);
    cudaGetSymbolAddress((void**)&ch,  g_ch);
    cudaGetSymbolAddress((void**)&xnh, g_xnh);
    cudaGetSymbolAddress((void**)&h1h, g_h1h);
    cudaGetSymbolAddress((void**)&wh,  g_wh);

    __half* w_caq = wh + 0 * DD * DD;
    __half* w_cak = wh + 1 * DD * DD;
    __half* w_cav = wh + 2 * DD * DD;
    __half* w_cao = wh + 3 * DD * DD;
    __half* w_saq = wh + 4 * DD * DD;
    __half* w_sak = wh + 5 * DD * DD;
    __half* w_sav = wh + 6 * DD * DD;
    __half* w_sao = wh + 7 * DD * DD;
    __half* w_m1  = wh + 8 * DD * DD;              // [512, 2048]
    __half* w_m2  = wh + 8 * DD * DD + DD * HID;   // [2048, 512]

    cudaFuncSetAttribute(gemm_mma, cudaFuncAttributeMaxDynamicSharedMemorySize,
                         GEMM_SMEM);
    cudaFuncSetAttribute(gemm_qkv, cudaFuncAttributeMaxDynamicSharedMemorySize,
                         GEMM_SMEM);
    cudaFuncSetAttribute(attn_mma, cudaFuncAttributeMaxDynamicSharedMemorySize,
                         ATT_SMEM);

    // ---- fp16 conversions (5 launches) ----
    const int CT = 256;
    {
        Cvt8Args ca;
        ca.src[0] = ca_wq; ca.dst[0] = w_caq;
        ca.src[1] = ca_wk; ca.dst[1] = w_cak;
        ca.src[2] = ca_wv; ca.dst[2] = w_cav;
        ca.src[3] = ca_wo; ca.dst[3] = w_cao;
        ca.src[4] = sa_wq; ca.dst[4] = w_saq;
        ca.src[5] = sa_wk; ca.dst[5] = w_sak;
        ca.src[6] = sa_wv; ca.dst[6] = w_sav;
        ca.src[7] = sa_wo; ca.dst[7] = w_sao;
        cvt16x8_k<<<dim3(DD*DD/4/CT, 8), CT>>>(ca, DD*DD);
    }
    cvt16_k<<<(MQ*DD/4 + CT-1)/CT, CT>>>(x,      xh,   MQ*DD);
    cvt16_k<<<(MK*DD/4 + CT-1)/CT, CT>>>(cross,  crh,  MK*DD);
    cvt16_k<<<(DD*HID/4 + CT-1)/CT, CT>>>(mlp_w1, w_m1, DD*HID);
    cvt16_k<<<(DD*HID/4 + CT-1)/CT, CT>>>(mlp_w2, w_m2, DD*HID);

    const dim3 blk(256);
    const dim3 gq(DD / 128, MQ / 128);        // 4 x 32
    const dim3 gh(HID / 128, MQ / 128);       // 16 x 32
    const dim3 ga(NQ / 128, HH, BB);          // 16 x 8 x 2

    // ---- cross-attention: fused QKV (z covers q from x, k/v from cross) ----
    {
        QkvArgs qa;
        qa.A[0] = xh;  qa.W[0] = w_caq; qa.bias[0] = ca_bq; qa.out[0] = qh; qa.M[0] = MQ;
        qa.A[1] = crh; qa.W[1] = w_cak; qa.bias[1] = ca_bk; qa.out[1] = kh; qa.M[1] = MK;
        qa.A[2] = crh; qa.W[2] = w_cav; qa.bias[2] = ca_bv; qa.out[2] = vh; qa.M[2] = MK;
        gemm_qkv<<<dim3(DD/128, MK/128, 3), blk, GEMM_SMEM>>>(qa, DD, DD);
    }
    attn_mma<<<ga, 256, ATT_SMEM>>>(qh, kh, vh, ch, NQ, NK);
    gemm_mma<<<gq, blk, GEMM_SMEM>>>(ch, w_cao, ca_bo, nullptr, xc, MQ, DD, DD, 0);

    // ---- LN1 + self-attention ----
    layernorm_k<<<MQ, 128>>>(xc, ln1_g, ln1_b, xnh);
    {
        QkvArgs qa;
        qa.A[0] = xnh; qa.W[0] = w_saq; qa.bias[0] = sa_bq; qa.out[0] = qh; qa.M[0] = MQ;
        qa.A[1] = xnh; qa.W[1] = w_sak; qa.bias[1] = sa_bk; qa.out[1] = kh; qa.M[1] = MQ;
        qa.A[2] = xnh; qa.W[2] = w_sav; qa.bias[2] = sa_bv; qa.out[2] = vh; qa.M[2] = MQ;
        gemm_qkv<<<dim3(DD/128, MQ/128, 3), blk, GEMM_SMEM>>>(qa, DD, DD);
    }
    attn_mma<<<ga, 256, ATT_SMEM>>>(qh, kh, vh, ch, NQ, NQ);
    gemm_mma<<<gq, blk, GEMM_SMEM>>>(ch, w_sao, sa_bo, xc, y, MQ, DD, DD, 2);  // y = xc + xs

    // ---- LN2 + MLP + residual ----
    layernorm_k<<<MQ, 128>>>(y, ln2_g, ln2_b, xnh);
    gemm_mma<<<gh, blk, GEMM_SMEM>>>(xnh, w_m1, mlp_b1, nullptr, h1h, MQ, HID, DD, 5);  // GELU->fp16
    gemm_mma<<<gq, blk, GEMM_SMEM>>>(h1h, w_m2, mlp_b2, y, out, MQ, DD, HID, 2);        // + y
}